// round 2
// baseline (speedup 1.0000x reference)
#include <cuda_runtime.h>
#include <math.h>

#define BB 32
#define NN 1024
#define NB 64
#define NT (NN / NB)
#define EPSV 1e-5f

// ---------------- scratch (device globals; no runtime allocation) ----------------
static __device__ float g_lap[(size_t)BB * NN * NN];     // Laplacian -> becomes inverse (134 MB)
static __device__ float g_P[BB * NB * NB];               // inverted diagonal block per batch
static __device__ float g_col[(size_t)BB * NN * NB];     // saved column block (8 MB)
static __device__ float g_colsum[BB * NN];
static __device__ float g_invdiag[BB * NN];
static __device__ float g_invcol0[BB * NN];

// ---------------- build ----------------
__global__ void build_colsum(const float* __restrict__ scores, const int* __restrict__ lengths) {
    int b = blockIdx.y;
    int j = blockIdx.x * 256 + threadIdx.x;
    int len = lengths[b];
    float acc = 0.f;
    if (j < len) {
        const float* sp = scores + (size_t)b * NN * NN + j;
        for (int i = 0; i < len; i++) {
            if (i != j) acc += expf(sp[(size_t)i * NN]) + EPSV;
        }
    }
    g_colsum[b * NN + j] = acc;
}

__global__ void build_fill(const float* __restrict__ scores, const int* __restrict__ lengths) {
    int b = blockIdx.y;
    int t = blockIdx.x * 256 + threadIdx.x;
    int i = t >> 10;
    int j = t & (NN - 1);
    int len = lengths[b];
    const float* sb = scores + (size_t)b * NN * NN;
    float v;
    if (i < len && j < len) {
        if (i == 0) {
            // row 0 override: exp(diag(S))[j]
            v = expf(sb[(size_t)j * NN + j]);
        } else if (i == j) {
            v = g_colsum[b * NN + j];
        } else {
            v = -(expf(sb[(size_t)i * NN + j]) + EPSV);
        }
    } else {
        v = (i == j) ? 1.f : 0.f;   // pad -> identity
    }
    g_lap[(size_t)b * NN * NN + t] = v;
}

// ---------------- blocked Gauss-Jordan inversion ----------------

// Invert diagonal block A_kk (64x64) with partial pivoting via augmented [A|I] in smem.
__global__ void gj_diaginv(int k) {
    __shared__ float M[NB][2 * NB + 1];
    __shared__ float s_colv[NB];
    __shared__ int s_piv;
    int b = blockIdx.x;
    int tid = threadIdx.x;  // 256
    const float* lapb = g_lap + (size_t)b * NN * NN;
    int kb = k * NB;

    for (int idx = tid; idx < NB * NB; idx += 256) {
        int r = idx >> 6, c = idx & (NB - 1);
        M[r][c] = lapb[(size_t)(kb + r) * NN + kb + c];
        M[r][NB + c] = (r == c) ? 1.f : 0.f;
    }
    __syncthreads();

    for (int kk = 0; kk < NB; kk++) {
        // pivot search (rows kk..63) by warp 0
        if (tid < 32) {
            float best = -1.f; int bp = kk;
            for (int r = kk + tid; r < NB; r += 32) {
                float v = fabsf(M[r][kk]);
                if (v > best) { best = v; bp = r; }
            }
            for (int off = 16; off; off >>= 1) {
                float ob = __shfl_xor_sync(0xffffffffu, best, off);
                int   op = __shfl_xor_sync(0xffffffffu, bp, off);
                if (ob > best) { best = ob; bp = op; }
            }
            if (tid == 0) s_piv = bp;
        }
        __syncthreads();
        int piv = s_piv;
        if (piv != kk && tid < 2 * NB) {
            float t = M[kk][tid]; M[kk][tid] = M[piv][tid]; M[piv][tid] = t;
        }
        __syncthreads();
        float pv = M[kk][kk];
        __syncthreads();
        float rpv = 1.f / pv;
        if (tid < 2 * NB) M[kk][tid] *= rpv;
        __syncthreads();
        if (tid < NB) s_colv[tid] = M[tid][kk];
        __syncthreads();
        // eliminate: each thread owns a fixed column, strided rows
        int c = tid & 127;
        float mkc = M[kk][c];
        for (int r = tid >> 7; r < NB; r += 2) {
            if (r != kk) M[r][c] -= s_colv[r] * mkc;
        }
        __syncthreads();
    }

    for (int idx = tid; idx < NB * NB; idx += 256) {
        int r = idx >> 6, c = idx & (NB - 1);
        g_P[((size_t)b * NB + r) * NB + c] = M[r][NB + c];
    }
}

// Save old column block A[:, kb:kb+NB] into g_col.
__global__ void gj_colcopy(int k) {
    int b = blockIdx.x, rb = blockIdx.y;
    int tid = threadIdx.x;
    int r = rb * NB + (tid >> 4);
    int c4 = (tid & 15) * 4;
    const float* lapb = g_lap + (size_t)b * NN * NN;
    float* colb = g_col + (size_t)b * NN * NB;
    #pragma unroll
    for (int rr = 0; rr < NB; rr += 16) {
        *(float4*)&colb[(size_t)(r + rr) * NB + c4] =
            *(const float4*)&lapb[(size_t)(r + rr) * NN + k * NB + c4];
    }
}

__device__ __forceinline__ void mm64(const float (*At)[NB], const float (*Bs)[NB],
                                     int r0, int c0, float4 acc[4]) {
    #pragma unroll
    for (int m = 0; m < NB; m++) {
        float4 a  = *(const float4*)&At[m][r0];
        float4 bv = *(const float4*)&Bs[m][c0];
        acc[0].x += a.x * bv.x; acc[0].y += a.x * bv.y; acc[0].z += a.x * bv.z; acc[0].w += a.x * bv.w;
        acc[1].x += a.y * bv.x; acc[1].y += a.y * bv.y; acc[1].z += a.y * bv.z; acc[1].w += a.y * bv.w;
        acc[2].x += a.z * bv.x; acc[2].y += a.z * bv.y; acc[2].z += a.z * bv.z; acc[2].w += a.z * bv.w;
        acc[3].x += a.w * bv.x; acc[3].y += a.w * bv.y; acc[3].z += a.w * bv.z; acc[3].w += a.w * bv.w;
    }
}

// Row-panel update: A_kj <- P * A_kj (j != k), A_kk <- P.
__global__ void gj_rowupd(int k) {
    int jt = blockIdx.x, b = blockIdx.y;
    int tid = threadIdx.x;
    float* lapb = g_lap + (size_t)b * NN * NN;
    int kb = k * NB, j0 = jt * NB;

    if (jt == k) {
        for (int idx = tid; idx < NB * NB; idx += 256) {
            int r = idx >> 6, c = idx & (NB - 1);
            lapb[(size_t)(kb + r) * NN + kb + c] = g_P[((size_t)b * NB + r) * NB + c];
        }
        return;
    }

    __shared__ __align__(16) float Pt[NB][NB];   // Pt[m][r] = P[r][m]
    __shared__ __align__(16) float Bs[NB][NB];
    int r = tid >> 4, c4 = (tid & 15) * 4;
    #pragma unroll
    for (int rr = 0; rr < NB; rr += 16) {
        float4 v = *(const float4*)&g_P[((size_t)b * NB + r + rr) * NB + c4];
        Pt[c4 + 0][r + rr] = v.x; Pt[c4 + 1][r + rr] = v.y;
        Pt[c4 + 2][r + rr] = v.z; Pt[c4 + 3][r + rr] = v.w;
        *(float4*)&Bs[r + rr][c4] = *(const float4*)&lapb[(size_t)(kb + r + rr) * NN + j0 + c4];
    }
    __syncthreads();

    int tx = tid & 15, ty = tid >> 4;
    int r0 = ty * 4, c0 = tx * 4;
    float4 acc[4] = {};
    mm64(Pt, Bs, r0, c0, acc);

    #pragma unroll
    for (int rr = 0; rr < 4; rr++) {
        *(float4*)&lapb[(size_t)(kb + r0 + rr) * NN + j0 + c0] = acc[rr];
    }
}

// Interior update: i != k rows.  j != k: A_ij -= col_i * A_kj ;  j == k: A_ik = -col_i * P.
__global__ void gj_interior(int k) {
    int jt = blockIdx.x, it = blockIdx.y, b = blockIdx.z;
    if (it == k) return;
    __shared__ __align__(16) float At[NB][NB];   // At[m][r] = col[i0+r][m]
    __shared__ __align__(16) float Bs[NB][NB];
    float* lapb = g_lap + (size_t)b * NN * NN;
    const float* colb = g_col + (size_t)b * NN * NB;
    int tid = threadIdx.x;
    int i0 = it * NB, j0 = jt * NB, kb = k * NB;

    int r = tid >> 4, c4 = (tid & 15) * 4;
    #pragma unroll
    for (int rr = 0; rr < NB; rr += 16) {
        float4 v = *(const float4*)&colb[(size_t)(i0 + r + rr) * NB + c4];
        At[c4 + 0][r + rr] = v.x; At[c4 + 1][r + rr] = v.y;
        At[c4 + 2][r + rr] = v.z; At[c4 + 3][r + rr] = v.w;
    }
    if (jt == k) {
        #pragma unroll
        for (int rr = 0; rr < NB; rr += 16)
            *(float4*)&Bs[r + rr][c4] = *(const float4*)&g_P[((size_t)b * NB + r + rr) * NB + c4];
    } else {
        #pragma unroll
        for (int rr = 0; rr < NB; rr += 16)
            *(float4*)&Bs[r + rr][c4] = *(const float4*)&lapb[(size_t)(kb + r + rr) * NN + j0 + c4];
    }
    __syncthreads();

    int tx = tid & 15, ty = tid >> 4;
    int r0 = ty * 4, c0 = tx * 4;
    float4 acc[4] = {};
    mm64(At, Bs, r0, c0, acc);

    if (jt == k) {
        #pragma unroll
        for (int rr = 0; rr < 4; rr++) {
            float4 w = make_float4(-acc[rr].x, -acc[rr].y, -acc[rr].z, -acc[rr].w);
            *(float4*)&lapb[(size_t)(i0 + r0 + rr) * NN + kb + c0] = w;
        }
    } else {
        #pragma unroll
        for (int rr = 0; rr < 4; rr++) {
            float4* dst = (float4*)&lapb[(size_t)(i0 + r0 + rr) * NN + j0 + c0];
            float4 old = *dst;
            old.x -= acc[rr].x; old.y -= acc[rr].y; old.z -= acc[rr].z; old.w -= acc[rr].w;
            *dst = old;
        }
    }
}

// ---------------- epilogue ----------------
__global__ void extract_diag() {
    int b = blockIdx.x;
    int t = threadIdx.x;  // 1024
    const float* invb = g_lap + (size_t)b * NN * NN;
    g_invdiag[b * NN + t] = invb[(size_t)t * NN + t];
    g_invcol0[b * NN + t] = invb[(size_t)t * NN];
}

__global__ void finalize(const float* __restrict__ scores, const int* __restrict__ lengths,
                         float* __restrict__ out) {
    __shared__ float sm[32][33];
    int b = blockIdx.z;
    int i0 = blockIdx.y * 32, j0 = blockIdx.x * 32;
    int tx = threadIdx.x, ty = threadIdx.y;
    const float* invb = g_lap + (size_t)b * NN * NN;

    // sm[jj][ii] = inv[j0+jj][i0+ii]  (coalesced load)
    sm[ty][tx] = invb[(size_t)(j0 + ty) * NN + i0 + tx];
    __syncthreads();

    int i = i0 + ty, j = j0 + tx;
    int len = lengths[b];
    float res = 0.f;
    if (i < len && j < len) {
        float e = expf(scores[(size_t)b * NN * NN + (size_t)i * NN + j]);
        float t1 = (j == 0) ? 0.f : e * g_invdiag[b * NN + j];
        float t2 = (i == 0) ? 0.f : e * sm[tx][ty];      // inv[j][i]
        float root = (i == j) ? e * g_invcol0[b * NN + i] : 0.f;
        res = t1 - t2 + root;
    }
    out[(size_t)b * NN * NN + (size_t)i * NN + j] = res;
}

// ---------------- launch ----------------
extern "C" void kernel_launch(void* const* d_in, const int* in_sizes, int n_in,
                              void* d_out, int out_size) {
    const float* scores = (const float*)d_in[0];
    const int* lengths = (const int*)d_in[1];
    float* out = (float*)d_out;

    build_colsum<<<dim3(NN / 256, BB), 256>>>(scores, lengths);
    build_fill<<<dim3(NN * NN / 256, BB), 256>>>(scores, lengths);

    for (int k = 0; k < NT; k++) {
        gj_diaginv<<<BB, 256>>>(k);
        gj_colcopy<<<dim3(BB, NT), 256>>>(k);
        gj_rowupd<<<dim3(NT, BB), 256>>>(k);
        gj_interior<<<dim3(NT, NT, BB), 256>>>(k);
    }

    extract_diag<<<BB, NN>>>();
    finalize<<<dim3(NN / 32, NN / 32, BB), dim3(32, 32)>>>(scores, lengths, out);
}

// round 4
// speedup vs baseline: 1.1471x; 1.1471x over previous
#include <cuda_runtime.h>
#include <math.h>
#include <stdint.h>

#define BB 32
#define NN 1024
#define NB 128
#define NT (NN / NB)
#define EPSV 1e-5f

// ---------------- scratch (device globals; no runtime allocation) ----------------
static __device__ float g_lap[(size_t)BB * NN * NN];     // Laplacian -> becomes inverse
static __device__ float g_P[(size_t)BB * NB * NB];       // inverted diagonal block per batch
static __device__ float g_col[(size_t)BB * NN * NB];     // saved column block
static __device__ float g_colsum[BB * NN];
static __device__ float g_invdiag[BB * NN];
static __device__ float g_invcol0[BB * NN];

// ---------------- build ----------------
__global__ void build_colsum(const float* __restrict__ scores, const int* __restrict__ lengths) {
    int b = blockIdx.y;
    int j = blockIdx.x * 256 + threadIdx.x;
    int len = lengths[b];
    float acc = 0.f;
    if (j < len) {
        const float* sp = scores + (size_t)b * NN * NN + j;
        for (int i = 0; i < len; i++) {
            if (i != j) acc += expf(sp[(size_t)i * NN]) + EPSV;
        }
    }
    g_colsum[b * NN + j] = acc;
}

__global__ void build_fill(const float* __restrict__ scores, const int* __restrict__ lengths) {
    int b = blockIdx.y;
    int t = blockIdx.x * 256 + threadIdx.x;
    int i = t >> 10;
    int j = t & (NN - 1);
    int len = lengths[b];
    const float* sb = scores + (size_t)b * NN * NN;
    float v;
    if (i < len && j < len) {
        if (i == 0) {
            v = expf(sb[(size_t)j * NN + j]);          // row 0: exp(diag)
        } else if (i == j) {
            v = g_colsum[b * NN + j];
        } else {
            v = -(expf(sb[(size_t)i * NN + j]) + EPSV);
        }
    } else {
        v = (i == j) ? 1.f : 0.f;                      // pad -> identity
    }
    g_lap[(size_t)b * NN * NN + t] = v;
}

// ---------------- diagonal block inverse (128x128, partial pivoting) ----------------
__global__ void gj_diaginv(int k) {
    extern __shared__ float M[];            // [128][260]
    __shared__ float s_colv[NB];
    __shared__ int s_piv;
    const int ST = 260;
    int b = blockIdx.x;
    int tid = threadIdx.x;                   // 512
    float* lapb = g_lap + (size_t)b * NN * NN;
    int kb = k * NB;

    for (int idx = tid; idx < NB * NB; idx += 512) {
        int r = idx >> 7, c = idx & 127;
        M[r * ST + c] = lapb[(size_t)(kb + r) * NN + kb + c];
        M[r * ST + NB + c] = (r == c) ? 1.f : 0.f;
    }
    __syncthreads();

    for (int kk = 0; kk < NB; kk++) {
        if (tid < 32) {
            float best = -1.f; int bp = kk;
            for (int r = kk + tid; r < NB; r += 32) {
                float v = fabsf(M[r * ST + kk]);
                if (v > best) { best = v; bp = r; }
            }
            for (int off = 16; off; off >>= 1) {
                float ob = __shfl_xor_sync(0xffffffffu, best, off);
                int   op = __shfl_xor_sync(0xffffffffu, bp, off);
                if (ob > best) { best = ob; bp = op; }
            }
            if (tid == 0) s_piv = bp;
        }
        __syncthreads();
        int piv = s_piv;
        if (piv != kk && tid < 2 * NB) {
            float t = M[kk * ST + tid]; M[kk * ST + tid] = M[piv * ST + tid]; M[piv * ST + tid] = t;
        }
        __syncthreads();
        float rpv = 1.f / M[kk * ST + kk];
        __syncthreads();
        if (tid < 2 * NB) M[kk * ST + tid] *= rpv;
        __syncthreads();
        if (tid < NB) s_colv[tid] = M[tid * ST + kk];
        __syncthreads();
        int fc = (tid & 63) * 4;
        float4 mk = *(float4*)&M[kk * ST + fc];
        for (int r = tid >> 6; r < NB; r += 8) {
            if (r == kk) continue;
            float cv = s_colv[r];
            float4* p = (float4*)&M[r * ST + fc];
            float4 v = *p;
            v.x -= cv * mk.x; v.y -= cv * mk.y; v.z -= cv * mk.z; v.w -= cv * mk.w;
            *p = v;
        }
        __syncthreads();
    }

    for (int idx = tid; idx < NB * NB; idx += 512) {
        int r = idx >> 7, c = idx & 127;
        g_P[((size_t)b * NB + r) * NB + c] = M[r * ST + NB + c];
    }
}

// ---------------- save column block ----------------
__global__ void gj_colcopy(int k) {
    int b = blockIdx.x, rb = blockIdx.y;
    int tid = threadIdx.x;                   // 256
    int r0 = rb * 128;
    const float* lapb = g_lap + (size_t)b * NN * NN;
    float* colb = g_col + (size_t)b * NN * NB;
    for (int idx = tid; idx < 128 * 32; idx += 256) {
        int r = r0 + (idx >> 5);
        int c4 = (idx & 31) * 4;
        *(float4*)&colb[(size_t)r * NB + c4] =
            *(const float4*)&lapb[(size_t)r * NN + k * NB + c4];
    }
}

// ---------------- tensor-core 128x128x128 GEMM core (3xTF32) ----------------
__device__ __forceinline__ uint32_t f2tf(float x) {
    uint32_t r; asm("cvt.rna.tf32.f32 %0, %1;" : "=r"(r) : "f"(x)); return r;
}
__device__ __forceinline__ void mma8(float4& d,
        uint32_t a0, uint32_t a1, uint32_t a2, uint32_t a3,
        uint32_t b0, uint32_t b1) {
    asm volatile("mma.sync.aligned.m16n8k8.row.col.f32.tf32.tf32.f32 "
        "{%0,%1,%2,%3}, {%4,%5,%6,%7}, {%8,%9}, {%0,%1,%2,%3};"
        : "+f"(d.x), "+f"(d.y), "+f"(d.z), "+f"(d.w)
        : "r"(a0), "r"(a1), "r"(a2), "r"(a3), "r"(b0), "r"(b1));
}

// C(128x128) += A(128x128, lda) * B(128x128, ldb). 128 threads.
// smem: 65536 bytes. Fragments pre-packed: one LDS.128 per fragment.
__device__ void gemm128(const float* __restrict__ Ag, int lda,
                        const float* __restrict__ Bg, int ldb,
                        float4 acc[4][8]) {
    extern __shared__ float4 sm4[];
    float4* Apk = sm4;          // ((c*8+mf)*2 + h)*32 + lane   [2048 f4]
    float4* Bpk = sm4 + 2048;   // ((c*16+nf))*32 + lane        [2048 f4]
    int tid = threadIdx.x;
    int lane = tid & 31, w = tid >> 5;
    int wy = w >> 1, wx = w & 1;

    for (int p = 0; p < 4; p++) {
        int k0 = p * 32;
        // ---- gather all global loads first (front-batched LDGs) ----
        float a_raw[8][4];
        #pragma unroll
        for (int it = 0; it < 8; it++) {
            int slot = it * 128 + tid;
            int l = slot & 31, mf = (slot >> 5) & 7, c = slot >> 8;
            int gg = l >> 2, tt = l & 3;
            int m = mf * 16 + gg, kk = k0 + c * 8 + tt;
            a_raw[it][0] = Ag[(size_t)m * lda + kk];
            a_raw[it][1] = Ag[(size_t)(m + 8) * lda + kk];
            a_raw[it][2] = Ag[(size_t)m * lda + kk + 4];
            a_raw[it][3] = Ag[(size_t)(m + 8) * lda + kk + 4];
        }
        float b_raw[16][2];
        #pragma unroll
        for (int it = 0; it < 16; it++) {
            int slot = it * 128 + tid;
            int l = slot & 31, nf = (slot >> 5) & 15, c = slot >> 9;
            int gg = l >> 2, tt = l & 3;
            int n = nf * 8 + gg, kk = k0 + c * 8 + tt;
            b_raw[it][0] = Bg[(size_t)kk * ldb + n];
            b_raw[it][1] = Bg[(size_t)(kk + 4) * ldb + n];
        }
        // ---- convert + pack A (hi/lo fragments) ----
        #pragma unroll
        for (int it = 0; it < 8; it++) {
            int slot = it * 128 + tid;
            int l = slot & 31, mf = (slot >> 5) & 7, c = slot >> 8;
            float a0 = a_raw[it][0], a1 = a_raw[it][1], a2 = a_raw[it][2], a3 = a_raw[it][3];
            uint32_t h0 = f2tf(a0), h1 = f2tf(a1), h2 = f2tf(a2), h3 = f2tf(a3);
            uint32_t l0 = f2tf(a0 - __uint_as_float(h0));
            uint32_t l1 = f2tf(a1 - __uint_as_float(h1));
            uint32_t l2 = f2tf(a2 - __uint_as_float(h2));
            uint32_t l3 = f2tf(a3 - __uint_as_float(h3));
            int base = (c * 8 + mf) * 64 + l;
            Apk[base]      = make_float4(__uint_as_float(h0), __uint_as_float(h1),
                                         __uint_as_float(h2), __uint_as_float(h3));
            Apk[base + 32] = make_float4(__uint_as_float(l0), __uint_as_float(l1),
                                         __uint_as_float(l2), __uint_as_float(l3));
        }
        // ---- convert + pack B ----
        #pragma unroll
        for (int it = 0; it < 16; it++) {
            int slot = it * 128 + tid;
            int l = slot & 31, nf = (slot >> 5) & 15, c = slot >> 9;
            float b0 = b_raw[it][0], b1 = b_raw[it][1];
            uint32_t h0 = f2tf(b0), h1 = f2tf(b1);
            uint32_t l0 = f2tf(b0 - __uint_as_float(h0));
            uint32_t l1 = f2tf(b1 - __uint_as_float(h1));
            Bpk[(c * 16 + nf) * 32 + l] =
                make_float4(__uint_as_float(h0), __uint_as_float(h1),
                            __uint_as_float(l0), __uint_as_float(l1));
        }
        __syncthreads();
        // ---- compute ----
        #pragma unroll
        for (int c = 0; c < 4; c++) {
            float4 af[4][2];
            #pragma unroll
            for (int i = 0; i < 4; i++) {
                int base = (c * 8 + wy * 4 + i) * 64 + lane;
                af[i][0] = Apk[base];
                af[i][1] = Apk[base + 32];
            }
            #pragma unroll
            for (int j = 0; j < 8; j++) {
                float4 bf = Bpk[(c * 16 + wx * 8 + j) * 32 + lane];
                uint32_t bh0 = __float_as_uint(bf.x), bh1 = __float_as_uint(bf.y);
                uint32_t bl0 = __float_as_uint(bf.z), bl1 = __float_as_uint(bf.w);
                #pragma unroll
                for (int i = 0; i < 4; i++) {
                    uint32_t ah0 = __float_as_uint(af[i][0].x), ah1 = __float_as_uint(af[i][0].y);
                    uint32_t ah2 = __float_as_uint(af[i][0].z), ah3 = __float_as_uint(af[i][0].w);
                    uint32_t al0 = __float_as_uint(af[i][1].x), al1 = __float_as_uint(af[i][1].y);
                    uint32_t al2 = __float_as_uint(af[i][1].z), al3 = __float_as_uint(af[i][1].w);
                    mma8(acc[i][j], ah0, ah1, ah2, ah3, bh0, bh1);
                    mma8(acc[i][j], ah0, ah1, ah2, ah3, bl0, bl1);
                    mma8(acc[i][j], al0, al1, al2, al3, bh0, bh1);
                }
            }
        }
        __syncthreads();
    }
}

// ---------------- row-panel update: A_kj <- P * A_kj ; A_kk <- P ----------------
__global__ void __launch_bounds__(128) gj_rowupd(int k) {
    int jt = blockIdx.x, b = blockIdx.y;
    float* lapb = g_lap + (size_t)b * NN * NN;
    int kb = k * NB, j0 = jt * NB;
    int tid = threadIdx.x;

    if (jt == k) {
        for (int idx = tid; idx < NB * NB / 4; idx += 128) {
            int r = idx >> 5, c4 = (idx & 31) * 4;
            *(float4*)&lapb[(size_t)(kb + r) * NN + kb + c4] =
                *(const float4*)&g_P[((size_t)b * NB + r) * NB + c4];
        }
        return;
    }

    float4 acc[4][8];
    #pragma unroll
    for (int i = 0; i < 4; i++)
        #pragma unroll
        for (int j = 0; j < 8; j++) acc[i][j] = make_float4(0.f, 0.f, 0.f, 0.f);

    gemm128(g_P + (size_t)b * NB * NB, NB, lapb + (size_t)kb * NN + j0, NN, acc);

    int lane = tid & 31, w = tid >> 5, wy = w >> 1, wx = w & 1;
    int g = lane >> 2, tg = lane & 3;
    #pragma unroll
    for (int i = 0; i < 4; i++) {
        int r0 = kb + wy * 64 + i * 16 + g;
        #pragma unroll
        for (int j = 0; j < 8; j++) {
            int cc = j0 + wx * 64 + j * 8 + 2 * tg;
            *(float2*)&lapb[(size_t)r0 * NN + cc]       = make_float2(acc[i][j].x, acc[i][j].y);
            *(float2*)&lapb[(size_t)(r0 + 8) * NN + cc] = make_float2(acc[i][j].z, acc[i][j].w);
        }
    }
}

// ---------------- interior update ----------------
__global__ void __launch_bounds__(128) gj_interior(int k) {
    int jt = blockIdx.x, it = blockIdx.y, b = blockIdx.z;
    if (it == k) return;
    float* lapb = g_lap + (size_t)b * NN * NN;
    const float* colb = g_col + (size_t)b * NN * NB;
    int i0 = it * NB, j0 = jt * NB, kb = k * NB;
    int tid = threadIdx.x;

    float4 acc[4][8];
    #pragma unroll
    for (int i = 0; i < 4; i++)
        #pragma unroll
        for (int j = 0; j < 8; j++) acc[i][j] = make_float4(0.f, 0.f, 0.f, 0.f);

    const float* Bg; int ldb;
    if (jt == k) { Bg = g_P + (size_t)b * NB * NB; ldb = NB; }
    else         { Bg = lapb + (size_t)kb * NN + j0; ldb = NN; }

    gemm128(colb + (size_t)i0 * NB, NB, Bg, ldb, acc);

    int lane = tid & 31, w = tid >> 5, wy = w >> 1, wx = w & 1;
    int g = lane >> 2, tg = lane & 3;

    if (jt == k) {
        #pragma unroll
        for (int i = 0; i < 4; i++) {
            int r0 = i0 + wy * 64 + i * 16 + g;
            #pragma unroll
            for (int j = 0; j < 8; j++) {
                int cc = kb + wx * 64 + j * 8 + 2 * tg;
                *(float2*)&lapb[(size_t)r0 * NN + cc]       = make_float2(-acc[i][j].x, -acc[i][j].y);
                *(float2*)&lapb[(size_t)(r0 + 8) * NN + cc] = make_float2(-acc[i][j].z, -acc[i][j].w);
            }
        }
    } else {
        #pragma unroll
        for (int i = 0; i < 4; i++) {
            int r0 = i0 + wy * 64 + i * 16 + g;
            #pragma unroll
            for (int j = 0; j < 8; j++) {
                int cc = j0 + wx * 64 + j * 8 + 2 * tg;
                float2* p0 = (float2*)&lapb[(size_t)r0 * NN + cc];
                float2* p1 = (float2*)&lapb[(size_t)(r0 + 8) * NN + cc];
                float2 o0 = *p0, o1 = *p1;
                o0.x -= acc[i][j].x; o0.y -= acc[i][j].y;
                o1.x -= acc[i][j].z; o1.y -= acc[i][j].w;
                *p0 = o0; *p1 = o1;
            }
        }
    }
}

// ---------------- epilogue ----------------
__global__ void extract_diag() {
    int b = blockIdx.x;
    int t = threadIdx.x;  // 1024
    const float* invb = g_lap + (size_t)b * NN * NN;
    g_invdiag[b * NN + t] = invb[(size_t)t * NN + t];
    g_invcol0[b * NN + t] = invb[(size_t)t * NN];
}

__global__ void finalize(const float* __restrict__ scores, const int* __restrict__ lengths,
                         float* __restrict__ out) {
    __shared__ float sm[32][33];
    int b = blockIdx.z;
    int i0 = blockIdx.y * 32, j0 = blockIdx.x * 32;
    int tx = threadIdx.x, ty = threadIdx.y;
    const float* invb = g_lap + (size_t)b * NN * NN;

    sm[ty][tx] = invb[(size_t)(j0 + ty) * NN + i0 + tx];
    __syncthreads();

    int i = i0 + ty, j = j0 + tx;
    int len = lengths[b];
    float res = 0.f;
    if (i < len && j < len) {
        float e = expf(scores[(size_t)b * NN * NN + (size_t)i * NN + j]);
        float t1 = (j == 0) ? 0.f : e * g_invdiag[b * NN + j];
        float t2 = (i == 0) ? 0.f : e * sm[tx][ty];      // inv[j][i]
        float root = (i == j) ? e * g_invcol0[b * NN + i] : 0.f;
        res = t1 - t2 + root;
    }
    out[(size_t)b * NN * NN + (size_t)i * NN + j] = res;
}

// ---------------- launch ----------------
extern "C" void kernel_launch(void* const* d_in, const int* in_sizes, int n_in,
                              void* d_out, int out_size) {
    const float* scores = (const float*)d_in[0];
    const int* lengths = (const int*)d_in[1];
    float* out = (float*)d_out;

    cudaFuncSetAttribute(gj_diaginv, cudaFuncAttributeMaxDynamicSharedMemorySize, 140 * 1024);
    cudaFuncSetAttribute(gj_rowupd, cudaFuncAttributeMaxDynamicSharedMemorySize, 64 * 1024);
    cudaFuncSetAttribute(gj_interior, cudaFuncAttributeMaxDynamicSharedMemorySize, 64 * 1024);

    build_colsum<<<dim3(NN / 256, BB), 256>>>(scores, lengths);
    build_fill<<<dim3(NN * NN / 256, BB), 256>>>(scores, lengths);

    const int DIAG_SMEM = 128 * 260 * 4;   // 133120
    const int GEMM_SMEM = 4096 * 16;       // 65536

    for (int k = 0; k < NT; k++) {
        gj_diaginv<<<BB, 512, DIAG_SMEM>>>(k);
        gj_colcopy<<<dim3(BB, 8), 256>>>(k);
        gj_rowupd<<<dim3(NT, BB), 128, GEMM_SMEM>>>(k);
        gj_interior<<<dim3(NT, NT, BB), 128, GEMM_SMEM>>>(k);
    }

    extract_diag<<<BB, NN>>>();
    finalize<<<dim3(NN / 32, NN / 32, BB), dim3(32, 32)>>>(scores, lengths, out);
}

// round 7
// speedup vs baseline: 1.3494x; 1.1763x over previous
#include <cuda_runtime.h>
#include <math.h>
#include <stdint.h>

#define BB 32
#define NN 1024
#define NB 128
#define NT (NN / NB)
#define EPSV 1e-5f

// ---------------- scratch (device globals; no runtime allocation) ----------------
static __device__ float g_lap[(size_t)BB * NN * NN];     // Laplacian -> becomes inverse
static __device__ float g_expS[(size_t)BB * NN * NN];    // exp(scores) on valid region
static __device__ float g_P[(size_t)BB * NB * NB];       // inverted diagonal block per batch
static __device__ float g_col[(size_t)BB * NN * NB];     // saved column block
static __device__ float g_colsum[BB * NN];
static __device__ float g_invdiag[BB * NN];
static __device__ float g_invcol0[BB * NN];

// ---------------- build ----------------
__global__ void build_exp(const float* __restrict__ scores, const int* __restrict__ lengths) {
    int b = blockIdx.y;
    int t = blockIdx.x * 256 + threadIdx.x;
    int i = t >> 10, j = t & (NN - 1);
    int len = lengths[b];
    if (i >= len) return;                       // uniform per block (block spans one i)
    if (j < len)
        g_expS[(size_t)b * NN * NN + t] = expf(scores[(size_t)b * NN * NN + t]);
}

// full column sums of expS over i < len (includes i==j; fill subtracts it)
__global__ void colsum_k(const int* __restrict__ lengths) {
    int b = blockIdx.x;
    int j = threadIdx.x;                        // 1024
    int len = lengths[b];
    const float* eb = g_expS + (size_t)b * NN * NN;
    float a0 = 0.f, a1 = 0.f, a2 = 0.f, a3 = 0.f;
    int i = 0;
    for (; i + 4 <= len; i += 4) {
        a0 += eb[(size_t)i * NN + j];
        a1 += eb[(size_t)(i + 1) * NN + j];
        a2 += eb[(size_t)(i + 2) * NN + j];
        a3 += eb[(size_t)(i + 3) * NN + j];
    }
    for (; i < len; i++) a0 += eb[(size_t)i * NN + j];
    g_colsum[b * NN + j] = (a0 + a1) + (a2 + a3);
}

__global__ void build_fill(const int* __restrict__ lengths) {
    int b = blockIdx.y;
    int t = blockIdx.x * 256 + threadIdx.x;
    int i = t >> 10, j = t & (NN - 1);
    int len = lengths[b];
    const float* eb = g_expS + (size_t)b * NN * NN;
    float v;
    if (i < len && j < len) {
        if (i == 0) {
            v = eb[(size_t)j * NN + j];                      // row 0: exp(diag)
        } else if (i == j) {
            v = g_colsum[b * NN + j] - eb[(size_t)j * NN + j] + (float)(len - 1) * EPSV;
        } else {
            v = -(eb[t] + EPSV);
        }
    } else {
        v = (i == j) ? 1.f : 0.f;                            // pad -> identity
    }
    g_lap[(size_t)b * NN * NN + t] = v;
}

// ---------------- diagonal block inverse (128x128, partial pivoting) ----------------
__global__ void gj_diaginv(int k, const int* __restrict__ lengths) {
    extern __shared__ float M[];            // [128][260]
    __shared__ float s_colv[NB];
    __shared__ int s_piv;
    const int ST = 260;
    int b = blockIdx.x;
    int len = lengths[b];
    int kb = k * NB;
    if (kb >= len) return;                  // pad block: identity, P unused
    int tid = threadIdx.x;                   // 512
    float* lapb = g_lap + (size_t)b * NN * NN;

    for (int idx = tid; idx < NB * NB; idx += 512) {
        int r = idx >> 7, c = idx & 127;
        M[r * ST + c] = lapb[(size_t)(kb + r) * NN + kb + c];
        M[r * ST + NB + c] = (r == c) ? 1.f : 0.f;
    }
    __syncthreads();

    for (int kk = 0; kk < NB; kk++) {
        if (tid < 32) {
            float best = -1.f; int bp = kk;
            for (int r = kk + tid; r < NB; r += 32) {
                float v = fabsf(M[r * ST + kk]);
                if (v > best) { best = v; bp = r; }
            }
            for (int off = 16; off; off >>= 1) {
                float ob = __shfl_xor_sync(0xffffffffu, best, off);
                int   op = __shfl_xor_sync(0xffffffffu, bp, off);
                if (ob > best) { best = ob; bp = op; }
            }
            if (tid == 0) s_piv = bp;
        }
        __syncthreads();
        int piv = s_piv;
        if (piv != kk && tid < 2 * NB) {
            float t = M[kk * ST + tid]; M[kk * ST + tid] = M[piv * ST + tid]; M[piv * ST + tid] = t;
        }
        __syncthreads();
        float rpv = 1.f / M[kk * ST + kk];
        __syncthreads();
        if (tid < 2 * NB) M[kk * ST + tid] *= rpv;
        __syncthreads();
        if (tid < NB) s_colv[tid] = M[tid * ST + kk];
        __syncthreads();
        int fc = (tid & 63) * 4;
        float4 mk = *(float4*)&M[kk * ST + fc];
        for (int r = tid >> 6; r < NB; r += 8) {
            if (r == kk) continue;
            float cv = s_colv[r];
            float4* p = (float4*)&M[r * ST + fc];
            float4 v = *p;
            v.x -= cv * mk.x; v.y -= cv * mk.y; v.z -= cv * mk.z; v.w -= cv * mk.w;
            *p = v;
        }
        __syncthreads();
    }

    for (int idx = tid; idx < NB * NB; idx += 512) {
        int r = idx >> 7, c = idx & 127;
        g_P[((size_t)b * NB + r) * NB + c] = M[r * ST + NB + c];
    }
}

// ---------------- save column block ----------------
__global__ void gj_colcopy(int k, const int* __restrict__ lengths) {
    int b = blockIdx.x, rb = blockIdx.y;
    int len = lengths[b];
    int kb = k * NB;
    int r0 = rb * NB;
    if (kb >= len || r0 >= len) return;     // pad: column block rows are zero / unread
    int tid = threadIdx.x;                   // 256
    const float* lapb = g_lap + (size_t)b * NN * NN;
    float* colb = g_col + (size_t)b * NN * NB;
    for (int idx = tid; idx < 128 * 32; idx += 256) {
        int r = r0 + (idx >> 5);
        int c4 = (idx & 31) * 4;
        *(float4*)&colb[(size_t)r * NB + c4] =
            *(const float4*)&lapb[(size_t)r * NN + kb + c4];
    }
}

// ---------------- legacy-mma 128x128x128 GEMM (3xTF32), 256 threads ----------------
__device__ __forceinline__ uint32_t f2tf(float x) {
    uint32_t r; asm("cvt.rna.tf32.f32 %0, %1;" : "=r"(r) : "f"(x)); return r;
}
__device__ __forceinline__ void mma8(float4& d,
        uint32_t a0, uint32_t a1, uint32_t a2, uint32_t a3,
        uint32_t b0, uint32_t b1) {
    asm volatile("mma.sync.aligned.m16n8k8.row.col.f32.tf32.tf32.f32 "
        "{%0,%1,%2,%3}, {%4,%5,%6,%7}, {%8,%9}, {%0,%1,%2,%3};"
        : "+f"(d.x), "+f"(d.y), "+f"(d.z), "+f"(d.w)
        : "r"(a0), "r"(a1), "r"(a2), "r"(a3), "r"(b0), "r"(b1));
}

// smem buffers: buf[q]: A at q*4096, B at q*4096+2048 (float4 units). total 8192 f4 = 128KB.
__device__ __forceinline__ void load_raw(const float* __restrict__ Ag, int lda,
                                         const float* __restrict__ Bg, int ldb,
                                         int k0, int tid,
                                         float a_raw[4][4], float b_raw[8][2]) {
    #pragma unroll
    for (int it = 0; it < 4; it++) {
        int slot = it * 256 + tid;
        int l = slot & 31, mf = (slot >> 5) & 7, c = slot >> 8;
        int gg = l >> 2, tt = l & 3;
        int m = mf * 16 + gg, kk = k0 + c * 8 + tt;
        a_raw[it][0] = Ag[(size_t)m * lda + kk];
        a_raw[it][1] = Ag[(size_t)(m + 8) * lda + kk];
        a_raw[it][2] = Ag[(size_t)m * lda + kk + 4];
        a_raw[it][3] = Ag[(size_t)(m + 8) * lda + kk + 4];
    }
    #pragma unroll
    for (int it = 0; it < 8; it++) {
        int slot = it * 256 + tid;
        int l = slot & 31, nf = (slot >> 5) & 15, c = slot >> 9;
        int gg = l >> 2, tt = l & 3;
        int n = nf * 8 + gg, kk = k0 + c * 8 + tt;
        b_raw[it][0] = Bg[(size_t)kk * ldb + n];
        b_raw[it][1] = Bg[(size_t)(kk + 4) * ldb + n];
    }
}

__device__ __forceinline__ void cvt_store(float4* __restrict__ Apk, float4* __restrict__ Bpk,
                                          int tid,
                                          const float a_raw[4][4], const float b_raw[8][2]) {
    #pragma unroll
    for (int it = 0; it < 4; it++) {
        int slot = it * 256 + tid;
        int l = slot & 31, mf = (slot >> 5) & 7, c = slot >> 8;
        float a0 = a_raw[it][0], a1 = a_raw[it][1], a2 = a_raw[it][2], a3 = a_raw[it][3];
        uint32_t h0 = f2tf(a0), h1 = f2tf(a1), h2 = f2tf(a2), h3 = f2tf(a3);
        uint32_t l0 = f2tf(a0 - __uint_as_float(h0));
        uint32_t l1 = f2tf(a1 - __uint_as_float(h1));
        uint32_t l2 = f2tf(a2 - __uint_as_float(h2));
        uint32_t l3 = f2tf(a3 - __uint_as_float(h3));
        int base = (c * 8 + mf) * 64 + l;
        Apk[base]      = make_float4(__uint_as_float(h0), __uint_as_float(h1),
                                     __uint_as_float(h2), __uint_as_float(h3));
        Apk[base + 32] = make_float4(__uint_as_float(l0), __uint_as_float(l1),
                                     __uint_as_float(l2), __uint_as_float(l3));
    }
    #pragma unroll
    for (int it = 0; it < 8; it++) {
        int slot = it * 256 + tid;
        int l = slot & 31, nf = (slot >> 5) & 15, c = slot >> 9;
        float b0 = b_raw[it][0], b1 = b_raw[it][1];
        uint32_t h0 = f2tf(b0), h1 = f2tf(b1);
        uint32_t l0 = f2tf(b0 - __uint_as_float(h0));
        uint32_t l1 = f2tf(b1 - __uint_as_float(h1));
        Bpk[(c * 16 + nf) * 32 + l] =
            make_float4(__uint_as_float(h0), __uint_as_float(h1),
                        __uint_as_float(l0), __uint_as_float(l1));
    }
}

__device__ __forceinline__ void compute_chunk(const float4* __restrict__ Apk,
                                              const float4* __restrict__ Bpk,
                                              int lane, int wy, int wx, float4 acc[2][8]) {
    #pragma unroll
    for (int c = 0; c < 4; c++) {
        float4 af[2][2];
        #pragma unroll
        for (int i = 0; i < 2; i++) {
            int base = (c * 8 + wy * 2 + i) * 64 + lane;
            af[i][0] = Apk[base];
            af[i][1] = Apk[base + 32];
        }
        #pragma unroll
        for (int j = 0; j < 8; j++) {
            float4 bf = Bpk[(c * 16 + wx * 8 + j) * 32 + lane];
            uint32_t bh0 = __float_as_uint(bf.x), bh1 = __float_as_uint(bf.y);
            uint32_t bl0 = __float_as_uint(bf.z), bl1 = __float_as_uint(bf.w);
            #pragma unroll
            for (int i = 0; i < 2; i++) {
                uint32_t ah0 = __float_as_uint(af[i][0].x), ah1 = __float_as_uint(af[i][0].y);
                uint32_t ah2 = __float_as_uint(af[i][0].z), ah3 = __float_as_uint(af[i][0].w);
                uint32_t al0 = __float_as_uint(af[i][1].x), al1 = __float_as_uint(af[i][1].y);
                uint32_t al2 = __float_as_uint(af[i][1].z), al3 = __float_as_uint(af[i][1].w);
                mma8(acc[i][j], ah0, ah1, ah2, ah3, bh0, bh1);
                mma8(acc[i][j], ah0, ah1, ah2, ah3, bl0, bl1);
                mma8(acc[i][j], al0, al1, al2, al3, bh0, bh1);
            }
        }
    }
}

// C(128x128) = A(128x128, K-major, lda) * B stored [k][j] (ldb). 256 threads, double-buffered.
__device__ void gemm256(const float* __restrict__ Ag, int lda,
                        const float* __restrict__ Bg, int ldb, float4 acc[2][8]) {
    extern __shared__ float4 sm4[];
    int tid = threadIdx.x;
    int lane = tid & 31, w = tid >> 5;
    int wy = w >> 1, wx = w & 1;

    float a_raw[4][4]; float b_raw[8][2];
    load_raw(Ag, lda, Bg, ldb, 0, tid, a_raw, b_raw);
    cvt_store(sm4, sm4 + 2048, tid, a_raw, b_raw);
    __syncthreads();

    #pragma unroll
    for (int p = 0; p < 4; p++) {
        const float4* Apk = sm4 + (p & 1) * 4096;
        const float4* Bpk = Apk + 2048;
        if (p < 3) load_raw(Ag, lda, Bg, ldb, (p + 1) * 32, tid, a_raw, b_raw);
        compute_chunk(Apk, Bpk, lane, wy, wx, acc);
        if (p < 3) {
            float4* nA = sm4 + ((p + 1) & 1) * 4096;
            cvt_store(nA, nA + 2048, tid, a_raw, b_raw);
        }
        __syncthreads();
    }
}

// ---------------- row-panel update: A_kj <- P * A_kj ; A_kk <- P ----------------
__global__ void __launch_bounds__(256) gj_rowupd(int k, const int* __restrict__ lengths) {
    int jt = blockIdx.x, b = blockIdx.y;
    int len = lengths[b];
    int kb = k * NB, j0 = jt * NB;
    if (kb >= len) return;                      // pad step: nothing changes
    float* lapb = g_lap + (size_t)b * NN * NN;
    int tid = threadIdx.x;

    if (jt == k) {
        for (int idx = tid; idx < NB * NB / 4; idx += 256) {
            int r = idx >> 5, c4 = (idx & 31) * 4;
            *(float4*)&lapb[(size_t)(kb + r) * NN + kb + c4] =
                *(const float4*)&g_P[((size_t)b * NB + r) * NB + c4];
        }
        return;
    }
    if (j0 >= len) return;                      // pad panel is zero: P*0 = 0

    float4 acc[2][8];
    #pragma unroll
    for (int i = 0; i < 2; i++)
        #pragma unroll
        for (int j = 0; j < 8; j++) acc[i][j] = make_float4(0.f, 0.f, 0.f, 0.f);

    gemm256(g_P + (size_t)b * NB * NB, NB, lapb + (size_t)kb * NN + j0, NN, acc);

    int lane = tid & 31, w = tid >> 5, wy = w >> 1, wx = w & 1;
    int gg = lane >> 2, tt = lane & 3;
    #pragma unroll
    for (int i = 0; i < 2; i++) {
        int r0 = kb + wy * 32 + i * 16 + gg;
        #pragma unroll
        for (int j = 0; j < 8; j++) {
            int cc = j0 + wx * 64 + j * 8 + 2 * tt;
            *(float2*)&lapb[(size_t)r0 * NN + cc]       = make_float2(acc[i][j].x, acc[i][j].y);
            *(float2*)&lapb[(size_t)(r0 + 8) * NN + cc] = make_float2(acc[i][j].z, acc[i][j].w);
        }
    }
}

// ---------------- interior update ----------------
__global__ void __launch_bounds__(256) gj_interior(int k, const int* __restrict__ lengths) {
    int jt = blockIdx.x, it = blockIdx.y, b = blockIdx.z;
    if (it == k) return;
    int len = lengths[b];
    int i0 = it * NB, j0 = jt * NB, kb = k * NB;
    if (kb >= len) return;                      // pad step
    if (i0 >= len) return;                      // col rows zero
    if (j0 >= len && jt != k) return;           // pad panel zero
    float* lapb = g_lap + (size_t)b * NN * NN;
    const float* colb = g_col + (size_t)b * NN * NB;
    int tid = threadIdx.x;

    float4 acc[2][8];
    #pragma unroll
    for (int i = 0; i < 2; i++)
        #pragma unroll
        for (int j = 0; j < 8; j++) acc[i][j] = make_float4(0.f, 0.f, 0.f, 0.f);

    const float* Bg; int ldb;
    if (jt == k) { Bg = g_P + (size_t)b * NB * NB; ldb = NB; }
    else         { Bg = lapb + (size_t)kb * NN + j0; ldb = NN; }

    gemm256(colb + (size_t)i0 * NB, NB, Bg, ldb, acc);

    int lane = tid & 31, w = tid >> 5, wy = w >> 1, wx = w & 1;
    int gg = lane >> 2, tt = lane & 3;

    if (jt == k) {
        #pragma unroll
        for (int i = 0; i < 2; i++) {
            int r0 = i0 + wy * 32 + i * 16 + gg;
            #pragma unroll
            for (int j = 0; j < 8; j++) {
                int cc = kb + wx * 64 + j * 8 + 2 * tt;
                *(float2*)&lapb[(size_t)r0 * NN + cc]       = make_float2(-acc[i][j].x, -acc[i][j].y);
                *(float2*)&lapb[(size_t)(r0 + 8) * NN + cc] = make_float2(-acc[i][j].z, -acc[i][j].w);
            }
        }
    } else {
        #pragma unroll
        for (int i = 0; i < 2; i++) {
            int r0 = i0 + wy * 32 + i * 16 + gg;
            #pragma unroll
            for (int j = 0; j < 8; j++) {
                int cc = j0 + wx * 64 + j * 8 + 2 * tt;
                float2* p0 = (float2*)&lapb[(size_t)r0 * NN + cc];
                float2* p1 = (float2*)&lapb[(size_t)(r0 + 8) * NN + cc];
                float2 o0 = *p0, o1 = *p1;
                o0.x -= acc[i][j].x; o0.y -= acc[i][j].y;
                o1.x -= acc[i][j].z; o1.y -= acc[i][j].w;
                *p0 = o0; *p1 = o1;
            }
        }
    }
}

// ---------------- epilogue ----------------
__global__ void extract_diag() {
    int b = blockIdx.x;
    int t = threadIdx.x;  // 1024
    const float* invb = g_lap + (size_t)b * NN * NN;
    g_invdiag[b * NN + t] = invb[(size_t)t * NN + t];
    g_invcol0[b * NN + t] = invb[(size_t)t * NN];
}

__global__ void finalize(const int* __restrict__ lengths, float* __restrict__ out) {
    __shared__ float sm[32][33];
    int b = blockIdx.z;
    int i0 = blockIdx.y * 32, j0 = blockIdx.x * 32;
    int tx = threadIdx.x, ty = threadIdx.y;
    const float* invb = g_lap + (size_t)b * NN * NN;

    sm[ty][tx] = invb[(size_t)(j0 + ty) * NN + i0 + tx];
    __syncthreads();

    int i = i0 + ty, j = j0 + tx;
    int len = lengths[b];
    float res = 0.f;
    if (i < len && j < len) {
        float e = g_expS[(size_t)b * NN * NN + (size_t)i * NN + j];
        float t1 = (j == 0) ? 0.f : e * g_invdiag[b * NN + j];
        float t2 = (i == 0) ? 0.f : e * sm[tx][ty];      // inv[j][i]
        float root = (i == j) ? e * g_invcol0[b * NN + i] : 0.f;
        res = t1 - t2 + root;
    }
    out[(size_t)b * NN * NN + (size_t)i * NN + j] = res;
}

// ---------------- launch ----------------
extern "C" void kernel_launch(void* const* d_in, const int* in_sizes, int n_in,
                              void* d_out, int out_size) {
    const float* scores = (const float*)d_in[0];
    const int* lengths = (const int*)d_in[1];
    float* out = (float*)d_out;

    const int DIAG_SMEM = 128 * 260 * 4;   // 133120
    const int GEMM_SMEM = 8192 * 16;       // 131072

    cudaFuncSetAttribute(gj_diaginv, cudaFuncAttributeMaxDynamicSharedMemorySize, 140 * 1024);
    cudaFuncSetAttribute(gj_rowupd, cudaFuncAttributeMaxDynamicSharedMemorySize, GEMM_SMEM);
    cudaFuncSetAttribute(gj_interior, cudaFuncAttributeMaxDynamicSharedMemorySize, GEMM_SMEM);

    build_exp<<<dim3(NN * NN / 256, BB), 256>>>(scores, lengths);
    colsum_k<<<BB, NN>>>(lengths);
    build_fill<<<dim3(NN * NN / 256, BB), 256>>>(lengths);

    for (int k = 0; k < NT; k++) {
        gj_diaginv<<<BB, 512, DIAG_SMEM>>>(k, lengths);
        gj_colcopy<<<dim3(BB, NT), 256>>>(k, lengths);
        gj_rowupd<<<dim3(NT, BB), 256, GEMM_SMEM>>>(k, lengths);
        gj_interior<<<dim3(NT, NT, BB), 256, GEMM_SMEM>>>(k, lengths);
    }

    extract_diag<<<BB, NN>>>();
    finalize<<<dim3(NN / 32, NN / 32, BB), dim3(32, 32)>>>(lengths, out);
}

// round 8
// speedup vs baseline: 1.4860x; 1.1013x over previous
#include <cuda_runtime.h>
#include <math.h>
#include <stdint.h>

#define BB 32
#define NN 1024
#define NB 128
#define NT (NN / NB)
#define EPSV 1e-5f

// ---------------- scratch (device globals; no runtime allocation) ----------------
static __device__ float g_lap[(size_t)BB * NN * NN];     // Laplacian -> becomes inverse
static __device__ float g_expS[(size_t)BB * NN * NN];    // exp(scores) on valid region
static __device__ float g_P[(size_t)BB * NB * NB];       // inverted diagonal block per batch
static __device__ float g_col[(size_t)BB * NN * NB];     // saved column block
static __device__ float g_colsum[BB * NN];
static __device__ float g_invdiag[BB * NN];
static __device__ float g_invcol0[BB * NN];

// ---------------- build ----------------
__global__ void build_exp(const float* __restrict__ scores, const int* __restrict__ lengths) {
    int b = blockIdx.y;
    int t = blockIdx.x * 256 + threadIdx.x;
    int i = t >> 10, j = t & (NN - 1);
    int len = lengths[b];
    if (i >= len) return;                       // uniform per block (block spans one i)
    if (j < len)
        g_expS[(size_t)b * NN * NN + t] = expf(scores[(size_t)b * NN * NN + t]);
}

// full column sums of expS over i < len (includes i==j; fill subtracts it)
__global__ void colsum_k(const int* __restrict__ lengths) {
    int b = blockIdx.x;
    int j = threadIdx.x;                        // 1024
    int len = lengths[b];
    const float* eb = g_expS + (size_t)b * NN * NN;
    float a0 = 0.f, a1 = 0.f, a2 = 0.f, a3 = 0.f;
    int i = 0;
    for (; i + 4 <= len; i += 4) {
        a0 += eb[(size_t)i * NN + j];
        a1 += eb[(size_t)(i + 1) * NN + j];
        a2 += eb[(size_t)(i + 2) * NN + j];
        a3 += eb[(size_t)(i + 3) * NN + j];
    }
    for (; i < len; i++) a0 += eb[(size_t)i * NN + j];
    g_colsum[b * NN + j] = (a0 + a1) + (a2 + a3);
}

__global__ void build_fill(const int* __restrict__ lengths) {
    int b = blockIdx.y;
    int t = blockIdx.x * 256 + threadIdx.x;
    int i = t >> 10, j = t & (NN - 1);
    int len = lengths[b];
    const float* eb = g_expS + (size_t)b * NN * NN;
    float v;
    if (i < len && j < len) {
        if (i == 0) {
            v = eb[(size_t)j * NN + j];                      // row 0: exp(diag)
        } else if (i == j) {
            v = g_colsum[b * NN + j] - eb[(size_t)j * NN + j] + (float)(len - 1) * EPSV;
        } else {
            v = -(eb[t] + EPSV);
        }
    } else {
        v = (i == j) ? 1.f : 0.f;                            // pad -> identity
    }
    g_lap[(size_t)b * NN * NN + t] = v;
}

// ---------------- diagonal block inverse (in-place GJ with partial pivoting) ----------------
// NR gaussj-style: A -> A^{-1} in place; row pivot swaps; reverse column-swap unscramble.
__global__ void gj_diaginv(int k, const int* __restrict__ lengths) {
    extern __shared__ float M[];             // [128][132] stride 132 (67.6 KB)
    __shared__ float s_colv[NB];
    __shared__ int s_pivarr[NB];
    __shared__ int s_piv;
    __shared__ float s_rpv;
    const int ST = 132;
    int b = blockIdx.x;
    int len = lengths[b];
    int kb = k * NB;
    if (kb >= len) return;                   // pad block: identity, P unused
    int tid = threadIdx.x;                    // 512
    float* lapb = g_lap + (size_t)b * NN * NN;

    for (int idx = tid; idx < NB * NB; idx += 512) {
        int r = idx >> 7, c = idx & 127;
        M[r * ST + c] = lapb[(size_t)(kb + r) * NN + kb + c];
    }
    __syncthreads();

    for (int kk = 0; kk < NB; kk++) {
        // ---- phase 1: warp 0: pivot search + swap-mapped column extract + 1/pivot ----
        if (tid < 32) {
            float best = -1.f; int bp = kk;
            for (int r = kk + tid; r < NB; r += 32) {
                float v = fabsf(M[r * ST + kk]);
                if (v > best) { best = v; bp = r; }
            }
            #pragma unroll
            for (int off = 16; off; off >>= 1) {
                float ob = __shfl_xor_sync(0xffffffffu, best, off);
                int   op = __shfl_xor_sync(0xffffffffu, bp, off);
                if (ob > best) { best = ob; bp = op; }
            }
            // bp now uniform across warp 0
            for (int r = tid; r < NB; r += 32) {
                int src = (r == kk) ? bp : (r == bp) ? kk : r;
                s_colv[r] = M[src * ST + kk];     // post-swap column kk (pre-scale)
            }
            if (tid == 0) {
                s_piv = bp;
                s_pivarr[kk] = bp;
                s_rpv = 1.f / M[bp * ST + kk];
            }
        }
        __syncthreads();
        int piv = s_piv;
        float rpv = s_rpv;
        // ---- phase 2: fused row swap (kk<->piv) + scale new row kk ----
        if (tid < NB) {
            int c = tid;
            float vkk = M[kk * ST + c];
            float vp  = M[piv * ST + c];
            if (piv != kk) M[piv * ST + c] = vkk;
            M[kk * ST + c] = (c == kk) ? rpv : vp * rpv;
        }
        __syncthreads();
        // ---- phase 3: rank-1 elimination; column kk becomes -f*rpv ----
        {
            int c4 = (tid & 31) * 4;
            float4 prow = *(float4*)&M[kk * ST + c4];
            bool hasK = (kk >= c4) && (kk < c4 + 4);
            int kl = kk - c4;
            #pragma unroll
            for (int q = 0; q < 8; q++) {
                int r = (tid >> 5) + q * 16;
                if (r == kk) continue;
                float f = s_colv[r];
                float4* p = (float4*)&M[r * ST + c4];
                float4 v = *p;
                v.x -= f * prow.x; v.y -= f * prow.y;
                v.z -= f * prow.z; v.w -= f * prow.w;
                if (hasK) ((float*)&v)[kl] = -f * rpv;
                *p = v;
            }
        }
        __syncthreads();
    }

    // ---- unscramble: reverse column swaps ----
    for (int kk = NB - 1; kk >= 0; kk--) {
        int p = s_pivarr[kk];
        if (p != kk) {
            if (tid < NB) {
                float t = M[tid * ST + kk];
                M[tid * ST + kk] = M[tid * ST + p];
                M[tid * ST + p] = t;
            }
            __syncthreads();
        }
    }

    for (int idx = tid; idx < NB * NB; idx += 512) {
        int r = idx >> 7, c = idx & 127;
        g_P[((size_t)b * NB + r) * NB + c] = M[r * ST + c];
    }
}

// ---------------- save column block ----------------
__global__ void gj_colcopy(int k, const int* __restrict__ lengths) {
    int b = blockIdx.x, rb = blockIdx.y;
    int len = lengths[b];
    int kb = k * NB;
    int r0 = rb * NB;
    if (kb >= len || r0 >= len) return;     // pad: column block rows are zero / unread
    int tid = threadIdx.x;                   // 256
    const float* lapb = g_lap + (size_t)b * NN * NN;
    float* colb = g_col + (size_t)b * NN * NB;
    for (int idx = tid; idx < 128 * 32; idx += 256) {
        int r = r0 + (idx >> 5);
        int c4 = (idx & 31) * 4;
        *(float4*)&colb[(size_t)r * NB + c4] =
            *(const float4*)&lapb[(size_t)r * NN + kb + c4];
    }
}

// ---------------- legacy-mma 128x128x128 GEMM (3xTF32), 256 threads ----------------
__device__ __forceinline__ uint32_t f2tf(float x) {
    uint32_t r; asm("cvt.rna.tf32.f32 %0, %1;" : "=r"(r) : "f"(x)); return r;
}
__device__ __forceinline__ void mma8(float4& d,
        uint32_t a0, uint32_t a1, uint32_t a2, uint32_t a3,
        uint32_t b0, uint32_t b1) {
    asm volatile("mma.sync.aligned.m16n8k8.row.col.f32.tf32.tf32.f32 "
        "{%0,%1,%2,%3}, {%4,%5,%6,%7}, {%8,%9}, {%0,%1,%2,%3};"
        : "+f"(d.x), "+f"(d.y), "+f"(d.z), "+f"(d.w)
        : "r"(a0), "r"(a1), "r"(a2), "r"(a3), "r"(b0), "r"(b1));
}

// smem buffers: buf[q]: A at q*4096, B at q*4096+2048 (float4 units). total 8192 f4 = 128KB.
__device__ __forceinline__ void load_raw(const float* __restrict__ Ag, int lda,
                                         const float* __restrict__ Bg, int ldb,
                                         int k0, int tid,
                                         float a_raw[4][4], float b_raw[8][2]) {
    #pragma unroll
    for (int it = 0; it < 4; it++) {
        int slot = it * 256 + tid;
        int l = slot & 31, mf = (slot >> 5) & 7, c = slot >> 8;
        int gg = l >> 2, tt = l & 3;
        int m = mf * 16 + gg, kk = k0 + c * 8 + tt;
        a_raw[it][0] = Ag[(size_t)m * lda + kk];
        a_raw[it][1] = Ag[(size_t)(m + 8) * lda + kk];
        a_raw[it][2] = Ag[(size_t)m * lda + kk + 4];
        a_raw[it][3] = Ag[(size_t)(m + 8) * lda + kk + 4];
    }
    #pragma unroll
    for (int it = 0; it < 8; it++) {
        int slot = it * 256 + tid;
        int l = slot & 31, nf = (slot >> 5) & 15, c = slot >> 9;
        int gg = l >> 2, tt = l & 3;
        int n = nf * 8 + gg, kk = k0 + c * 8 + tt;
        b_raw[it][0] = Bg[(size_t)kk * ldb + n];
        b_raw[it][1] = Bg[(size_t)(kk + 4) * ldb + n];
    }
}

__device__ __forceinline__ void cvt_store(float4* __restrict__ Apk, float4* __restrict__ Bpk,
                                          int tid,
                                          const float a_raw[4][4], const float b_raw[8][2]) {
    #pragma unroll
    for (int it = 0; it < 4; it++) {
        int slot = it * 256 + tid;
        int l = slot & 31, mf = (slot >> 5) & 7, c = slot >> 8;
        float a0 = a_raw[it][0], a1 = a_raw[it][1], a2 = a_raw[it][2], a3 = a_raw[it][3];
        uint32_t h0 = f2tf(a0), h1 = f2tf(a1), h2 = f2tf(a2), h3 = f2tf(a3);
        uint32_t l0 = f2tf(a0 - __uint_as_float(h0));
        uint32_t l1 = f2tf(a1 - __uint_as_float(h1));
        uint32_t l2 = f2tf(a2 - __uint_as_float(h2));
        uint32_t l3 = f2tf(a3 - __uint_as_float(h3));
        int base = (c * 8 + mf) * 64 + l;
        Apk[base]      = make_float4(__uint_as_float(h0), __uint_as_float(h1),
                                     __uint_as_float(h2), __uint_as_float(h3));
        Apk[base + 32] = make_float4(__uint_as_float(l0), __uint_as_float(l1),
                                     __uint_as_float(l2), __uint_as_float(l3));
    }
    #pragma unroll
    for (int it = 0; it < 8; it++) {
        int slot = it * 256 + tid;
        int l = slot & 31, nf = (slot >> 5) & 15, c = slot >> 9;
        float b0 = b_raw[it][0], b1 = b_raw[it][1];
        uint32_t h0 = f2tf(b0), h1 = f2tf(b1);
        uint32_t l0 = f2tf(b0 - __uint_as_float(h0));
        uint32_t l1 = f2tf(b1 - __uint_as_float(h1));
        Bpk[(c * 16 + nf) * 32 + l] =
            make_float4(__uint_as_float(h0), __uint_as_float(h1),
                        __uint_as_float(l0), __uint_as_float(l1));
    }
}

__device__ __forceinline__ void compute_chunk(const float4* __restrict__ Apk,
                                              const float4* __restrict__ Bpk,
                                              int lane, int wy, int wx, float4 acc[2][8]) {
    #pragma unroll
    for (int c = 0; c < 4; c++) {
        float4 af[2][2];
        #pragma unroll
        for (int i = 0; i < 2; i++) {
            int base = (c * 8 + wy * 2 + i) * 64 + lane;
            af[i][0] = Apk[base];
            af[i][1] = Apk[base + 32];
        }
        #pragma unroll
        for (int j = 0; j < 8; j++) {
            float4 bf = Bpk[(c * 16 + wx * 8 + j) * 32 + lane];
            uint32_t bh0 = __float_as_uint(bf.x), bh1 = __float_as_uint(bf.y);
            uint32_t bl0 = __float_as_uint(bf.z), bl1 = __float_as_uint(bf.w);
            #pragma unroll
            for (int i = 0; i < 2; i++) {
                uint32_t ah0 = __float_as_uint(af[i][0].x), ah1 = __float_as_uint(af[i][0].y);
                uint32_t ah2 = __float_as_uint(af[i][0].z), ah3 = __float_as_uint(af[i][0].w);
                uint32_t al0 = __float_as_uint(af[i][1].x), al1 = __float_as_uint(af[i][1].y);
                uint32_t al2 = __float_as_uint(af[i][1].z), al3 = __float_as_uint(af[i][1].w);
                mma8(acc[i][j], ah0, ah1, ah2, ah3, bh0, bh1);
                mma8(acc[i][j], ah0, ah1, ah2, ah3, bl0, bl1);
                mma8(acc[i][j], al0, al1, al2, al3, bh0, bh1);
            }
        }
    }
}

// C(128x128) = A(128x128, K-major, lda) * B stored [k][j] (ldb). 256 threads, double-buffered.
__device__ void gemm256(const float* __restrict__ Ag, int lda,
                        const float* __restrict__ Bg, int ldb, float4 acc[2][8]) {
    extern __shared__ float4 sm4[];
    int tid = threadIdx.x;
    int lane = tid & 31, w = tid >> 5;
    int wy = w >> 1, wx = w & 1;

    float a_raw[4][4]; float b_raw[8][2];
    load_raw(Ag, lda, Bg, ldb, 0, tid, a_raw, b_raw);
    cvt_store(sm4, sm4 + 2048, tid, a_raw, b_raw);
    __syncthreads();

    #pragma unroll
    for (int p = 0; p < 4; p++) {
        const float4* Apk = sm4 + (p & 1) * 4096;
        const float4* Bpk = Apk + 2048;
        if (p < 3) load_raw(Ag, lda, Bg, ldb, (p + 1) * 32, tid, a_raw, b_raw);
        compute_chunk(Apk, Bpk, lane, wy, wx, acc);
        if (p < 3) {
            float4* nA = sm4 + ((p + 1) & 1) * 4096;
            cvt_store(nA, nA + 2048, tid, a_raw, b_raw);
        }
        __syncthreads();
    }
}

// ---------------- row-panel update: A_kj <- P * A_kj ; A_kk <- P ----------------
__global__ void __launch_bounds__(256) gj_rowupd(int k, const int* __restrict__ lengths) {
    int jt = blockIdx.x, b = blockIdx.y;
    int len = lengths[b];
    int kb = k * NB, j0 = jt * NB;
    if (kb >= len) return;                      // pad step: nothing changes
    float* lapb = g_lap + (size_t)b * NN * NN;
    int tid = threadIdx.x;

    if (jt == k) {
        for (int idx = tid; idx < NB * NB / 4; idx += 256) {
            int r = idx >> 5, c4 = (idx & 31) * 4;
            *(float4*)&lapb[(size_t)(kb + r) * NN + kb + c4] =
                *(const float4*)&g_P[((size_t)b * NB + r) * NB + c4];
        }
        return;
    }
    if (j0 >= len) return;                      // pad panel is zero: P*0 = 0

    float4 acc[2][8];
    #pragma unroll
    for (int i = 0; i < 2; i++)
        #pragma unroll
        for (int j = 0; j < 8; j++) acc[i][j] = make_float4(0.f, 0.f, 0.f, 0.f);

    gemm256(g_P + (size_t)b * NB * NB, NB, lapb + (size_t)kb * NN + j0, NN, acc);

    int lane = tid & 31, w = tid >> 5, wy = w >> 1, wx = w & 1;
    int gg = lane >> 2, tt = lane & 3;
    #pragma unroll
    for (int i = 0; i < 2; i++) {
        int r0 = kb + wy * 32 + i * 16 + gg;
        #pragma unroll
        for (int j = 0; j < 8; j++) {
            int cc = j0 + wx * 64 + j * 8 + 2 * tt;
            *(float2*)&lapb[(size_t)r0 * NN + cc]       = make_float2(acc[i][j].x, acc[i][j].y);
            *(float2*)&lapb[(size_t)(r0 + 8) * NN + cc] = make_float2(acc[i][j].z, acc[i][j].w);
        }
    }
}

// ---------------- interior update ----------------
__global__ void __launch_bounds__(256) gj_interior(int k, const int* __restrict__ lengths) {
    int jt = blockIdx.x, it = blockIdx.y, b = blockIdx.z;
    if (it == k) return;
    int len = lengths[b];
    int i0 = it * NB, j0 = jt * NB, kb = k * NB;
    if (kb >= len) return;                      // pad step
    if (i0 >= len) return;                      // col rows zero
    if (j0 >= len && jt != k) return;           // pad panel zero
    float* lapb = g_lap + (size_t)b * NN * NN;
    const float* colb = g_col + (size_t)b * NN * NB;
    int tid = threadIdx.x;

    float4 acc[2][8];
    #pragma unroll
    for (int i = 0; i < 2; i++)
        #pragma unroll
        for (int j = 0; j < 8; j++) acc[i][j] = make_float4(0.f, 0.f, 0.f, 0.f);

    const float* Bg; int ldb;
    if (jt == k) { Bg = g_P + (size_t)b * NB * NB; ldb = NB; }
    else         { Bg = lapb + (size_t)kb * NN + j0; ldb = NN; }

    gemm256(colb + (size_t)i0 * NB, NB, Bg, ldb, acc);

    int lane = tid & 31, w = tid >> 5, wy = w >> 1, wx = w & 1;
    int gg = lane >> 2, tt = lane & 3;

    if (jt == k) {
        #pragma unroll
        for (int i = 0; i < 2; i++) {
            int r0 = i0 + wy * 32 + i * 16 + gg;
            #pragma unroll
            for (int j = 0; j < 8; j++) {
                int cc = kb + wx * 64 + j * 8 + 2 * tt;
                *(float2*)&lapb[(size_t)r0 * NN + cc]       = make_float2(-acc[i][j].x, -acc[i][j].y);
                *(float2*)&lapb[(size_t)(r0 + 8) * NN + cc] = make_float2(-acc[i][j].z, -acc[i][j].w);
            }
        }
    } else {
        #pragma unroll
        for (int i = 0; i < 2; i++) {
            int r0 = i0 + wy * 32 + i * 16 + gg;
            #pragma unroll
            for (int j = 0; j < 8; j++) {
                int cc = j0 + wx * 64 + j * 8 + 2 * tt;
                float2* p0 = (float2*)&lapb[(size_t)r0 * NN + cc];
                float2* p1 = (float2*)&lapb[(size_t)(r0 + 8) * NN + cc];
                float2 o0 = *p0, o1 = *p1;
                o0.x -= acc[i][j].x; o0.y -= acc[i][j].y;
                o1.x -= acc[i][j].z; o1.y -= acc[i][j].w;
                *p0 = o0; *p1 = o1;
            }
        }
    }
}

// ---------------- epilogue ----------------
__global__ void extract_diag() {
    int b = blockIdx.x;
    int t = threadIdx.x;  // 1024
    const float* invb = g_lap + (size_t)b * NN * NN;
    g_invdiag[b * NN + t] = invb[(size_t)t * NN + t];
    g_invcol0[b * NN + t] = invb[(size_t)t * NN];
}

__global__ void finalize(const int* __restrict__ lengths, float* __restrict__ out) {
    __shared__ float sm[32][33];
    int b = blockIdx.z;
    int i0 = blockIdx.y * 32, j0 = blockIdx.x * 32;
    int tx = threadIdx.x, ty = threadIdx.y;
    const float* invb = g_lap + (size_t)b * NN * NN;

    sm[ty][tx] = invb[(size_t)(j0 + ty) * NN + i0 + tx];
    __syncthreads();

    int i = i0 + ty, j = j0 + tx;
    int len = lengths[b];
    float res = 0.f;
    if (i < len && j < len) {
        float e = g_expS[(size_t)b * NN * NN + (size_t)i * NN + j];
        float t1 = (j == 0) ? 0.f : e * g_invdiag[b * NN + j];
        float t2 = (i == 0) ? 0.f : e * sm[tx][ty];      // inv[j][i]
        float root = (i == j) ? e * g_invcol0[b * NN + i] : 0.f;
        res = t1 - t2 + root;
    }
    out[(size_t)b * NN * NN + (size_t)i * NN + j] = res;
}

// ---------------- launch ----------------
extern "C" void kernel_launch(void* const* d_in, const int* in_sizes, int n_in,
                              void* d_out, int out_size) {
    const float* scores = (const float*)d_in[0];
    const int* lengths = (const int*)d_in[1];
    float* out = (float*)d_out;

    const int DIAG_SMEM = 128 * 132 * 4;   // 67584
    const int GEMM_SMEM = 8192 * 16;       // 131072

    cudaFuncSetAttribute(gj_diaginv, cudaFuncAttributeMaxDynamicSharedMemorySize, DIAG_SMEM);
    cudaFuncSetAttribute(gj_rowupd, cudaFuncAttributeMaxDynamicSharedMemorySize, GEMM_SMEM);
    cudaFuncSetAttribute(gj_interior, cudaFuncAttributeMaxDynamicSharedMemorySize, GEMM_SMEM);

    build_exp<<<dim3(NN * NN / 256, BB), 256>>>(scores, lengths);
    colsum_k<<<BB, NN>>>(lengths);
    build_fill<<<dim3(NN * NN / 256, BB), 256>>>(lengths);

    for (int k = 0; k < NT; k++) {
        gj_diaginv<<<BB, 512, DIAG_SMEM>>>(k, lengths);
        gj_colcopy<<<dim3(BB, NT), 256>>>(k, lengths);
        gj_rowupd<<<dim3(NT, BB), 256, GEMM_SMEM>>>(k, lengths);
        gj_interior<<<dim3(NT, NT, BB), 256, GEMM_SMEM>>>(k, lengths);
    }

    extract_diag<<<BB, NN>>>();
    finalize<<<dim3(NN / 32, NN / 32, BB), dim3(32, 32)>>>(lengths, out);
}

// round 10
// speedup vs baseline: 1.8728x; 1.2602x over previous
#include <cuda_runtime.h>
#include <math.h>
#include <stdint.h>

#define BB 32
#define NN 1024
#define NB 128
#define NT (NN / NB)
#define EPSV 1e-5f

// ---------------- scratch (device globals; no runtime allocation) ----------------
static __device__ float g_lap[(size_t)BB * NN * NN];     // Laplacian -> becomes inverse
static __device__ float g_expS[(size_t)BB * NN * NN];    // exp(scores) on valid region
static __device__ float g_P[(size_t)BB * NB * NB];       // inverted diagonal block per batch
static __device__ float g_col[(size_t)BB * NN * NB];     // saved column block
static __device__ float g_colsum[BB * NN];
static __device__ float g_invdiag[BB * NN];
static __device__ float g_invcol0[BB * NN];

// ---------------- build ----------------
__global__ void build_exp(const float* __restrict__ scores, const int* __restrict__ lengths) {
    int b = blockIdx.y;
    int t = blockIdx.x * 256 + threadIdx.x;
    int i = t >> 10, j = t & (NN - 1);
    int len = lengths[b];
    if (i >= len) return;                       // uniform per block (block spans one i)
    if (j < len)
        g_expS[(size_t)b * NN * NN + t] = expf(scores[(size_t)b * NN * NN + t]);
}

// full column sums of expS over i < len (includes i==j; fill subtracts it)
__global__ void colsum_k(const int* __restrict__ lengths) {
    int b = blockIdx.x;
    int j = threadIdx.x;                        // 1024
    int len = lengths[b];
    const float* eb = g_expS + (size_t)b * NN * NN;
    float a0 = 0.f, a1 = 0.f, a2 = 0.f, a3 = 0.f;
    int i = 0;
    for (; i + 4 <= len; i += 4) {
        a0 += eb[(size_t)i * NN + j];
        a1 += eb[(size_t)(i + 1) * NN + j];
        a2 += eb[(size_t)(i + 2) * NN + j];
        a3 += eb[(size_t)(i + 3) * NN + j];
    }
    for (; i < len; i++) a0 += eb[(size_t)i * NN + j];
    g_colsum[b * NN + j] = (a0 + a1) + (a2 + a3);
}

__global__ void build_fill(const int* __restrict__ lengths) {
    int b = blockIdx.y;
    int t = blockIdx.x * 256 + threadIdx.x;
    int i = t >> 10, j = t & (NN - 1);
    int len = lengths[b];
    const float* eb = g_expS + (size_t)b * NN * NN;
    float v;
    if (i < len && j < len) {
        if (i == 0) {
            v = eb[(size_t)j * NN + j];                      // row 0: exp(diag)
        } else if (i == j) {
            v = g_colsum[b * NN + j] - eb[(size_t)j * NN + j] + (float)(len - 1) * EPSV;
        } else {
            v = -(eb[t] + EPSV);
        }
    } else {
        v = (i == j) ? 1.f : 0.f;                            // pad -> identity
    }
    g_lap[(size_t)b * NN * NN + t] = v;
}

// ---------------- diagonal block inverse: 2-level blocked GJ ----------------
// Outer: 4 steps of block size 32 over the 128x128 tile (block GJ, in place in smem).
// Inner: warp-0 register-resident 32x32 pivoted inverse (NR, shuffle-based).
__global__ void gj_diaginv(int k, const int* __restrict__ lengths) {
    extern __shared__ float M[];              // [128][132]
    __shared__ float rowbuf[32 * 132];        // saved row panel (R_old)
    __shared__ float colbuf[128 * 32];        // saved col panel (C_old)
    __shared__ float bbuf[32 * 33];           // B = inv(D)
    __shared__ int s_ipiv[32];
    __shared__ int s_perm[32];
    __shared__ int s_perminv[32];
    const int ST = 132;
    int b = blockIdx.x;
    int len = lengths[b];
    int kb = k * NB;
    if (kb >= len) return;                    // pad block: identity, P unused
    int tid = threadIdx.x;                     // 512
    float* lapb = g_lap + (size_t)b * NN * NN;

    for (int idx = tid; idx < NB * NB; idx += 512) {
        int r = idx >> 7, c = idx & 127;
        M[r * ST + c] = lapb[(size_t)(kb + r) * NN + kb + c];
    }
    __syncthreads();

    for (int s0 = 0; s0 < NB; s0 += 32) {
        // ---- phase A: save C_old (all rows, s-cols) and R_old (s-rows, all cols) ----
        {
            // colbuf: 128x32 floats = 1024 float4 slots
            int slot = tid;                    // 512 threads, 2 slots each
            #pragma unroll
            for (int q = 0; q < 2; q++, slot += 512) {
                int r = slot >> 3, c4 = (slot & 7) * 4;
                *(float4*)&colbuf[r * 32 + c4] = *(const float4*)&M[r * ST + s0 + c4];
            }
            // rowbuf: 32x128 floats = 1024 float4 slots
            slot = tid;
            #pragma unroll
            for (int q = 0; q < 2; q++, slot += 512) {
                int r = slot >> 5, c4 = (slot & 31) * 4;
                *(float4*)&rowbuf[r * ST + c4] = *(const float4*)&M[(s0 + r) * ST + c4];
            }
        }
        __syncthreads();

        // ---- phase B: warp 0 inverts D (32x32) in registers ----
        if (tid < 32) {
            int lane = tid;
            float v[32];
            #pragma unroll
            for (int c = 0; c < 32; c++) v[c] = M[(s0 + lane) * ST + s0 + c];

            #pragma unroll
            for (int kk = 0; kk < 32; kk++) {
                float best = (lane >= kk) ? fabsf(v[kk]) : -1.0f;
                int bp = lane;
                #pragma unroll
                for (int off = 16; off; off >>= 1) {
                    float ob = __shfl_xor_sync(0xffffffffu, best, off);
                    int   op = __shfl_xor_sync(0xffffffffu, bp, off);
                    if (ob > best) { best = ob; bp = op; }
                }
                if (lane == 0) s_ipiv[kk] = bp;
                int src = (lane == kk) ? bp : (lane == bp) ? kk : lane;
                #pragma unroll
                for (int c = 0; c < 32; c++) v[c] = __shfl_sync(0xffffffffu, v[c], src);
                if (lane == kk) {
                    float rpv = 1.0f / v[kk];
                    v[kk] = 1.0f;
                    #pragma unroll
                    for (int c = 0; c < 32; c++) v[c] *= rpv;
                }
                float f = v[kk];
                if (lane != kk) v[kk] = 0.0f;
                #pragma unroll
                for (int c = 0; c < 32; c++) {
                    float pr = __shfl_sync(0xffffffffu, v[c], kk);
                    if (lane != kk) v[c] -= f * pr;
                }
            }
            // reverse column-swap permutation
            if (lane == 0) {
                #pragma unroll
                for (int c = 0; c < 32; c++) s_perm[c] = c;
                for (int kk = 31; kk >= 0; kk--) {
                    int p = s_ipiv[kk];
                    int t = s_perm[kk]; s_perm[kk] = s_perm[p]; s_perm[p] = t;
                }
                for (int a = 0; a < 32; a++) s_perminv[s_perm[a]] = a;
            }
            __syncwarp();
            #pragma unroll
            for (int c = 0; c < 32; c++) bbuf[lane * 33 + s_perminv[c]] = v[c];
        }
        __syncthreads();

        // ---- phase C: row panel.  s-rows: cols in s -> B ; else B * R_old ----
        {
            int r3 = tid >> 4;                 // 0..31
            int cseg = (tid & 15) * 8;         // 8 cols
            float4 acc0 = make_float4(0.f, 0.f, 0.f, 0.f);
            float4 acc1 = make_float4(0.f, 0.f, 0.f, 0.f);
            if (cseg == s0 || cseg == s0 + 8 || cseg == s0 + 16 || cseg == s0 + 24) {
                // inside s-block: write B
                int cb = cseg - s0;
                #pragma unroll
                for (int q = 0; q < 8; q++)
                    M[(s0 + r3) * ST + cseg + q] = bbuf[r3 * 33 + cb + q];
            } else {
                #pragma unroll
                for (int t32 = 0; t32 < 32; t32++) {
                    float bb = bbuf[r3 * 33 + t32];
                    float4 ra = *(const float4*)&rowbuf[t32 * ST + cseg];
                    float4 rb = *(const float4*)&rowbuf[t32 * ST + cseg + 4];
                    acc0.x += bb * ra.x; acc0.y += bb * ra.y; acc0.z += bb * ra.z; acc0.w += bb * ra.w;
                    acc1.x += bb * rb.x; acc1.y += bb * rb.y; acc1.z += bb * rb.z; acc1.w += bb * rb.w;
                }
                *(float4*)&M[(s0 + r3) * ST + cseg]     = acc0;
                *(float4*)&M[(s0 + r3) * ST + cseg + 4] = acc1;
            }
        }
        __syncthreads();

        // ---- phase D: other rows.  acc = C_old * M[s-rows];  c in s: -acc ; else M -= acc ----
        {
            int idx0 = tid >> 5;               // 0..15
            int c0 = (tid & 31) * 4;           // 4 cols
            float4 acc[6];
            #pragma unroll
            for (int q = 0; q < 6; q++) acc[q] = make_float4(0.f, 0.f, 0.f, 0.f);
            int rr[6];
            #pragma unroll
            for (int q = 0; q < 6; q++) {
                int rq = idx0 + 16 * q;        // 0..95
                rr[q] = (rq < s0) ? rq : rq + 32;
            }
            #pragma unroll
            for (int t32 = 0; t32 < 32; t32++) {
                float4 pr = *(const float4*)&M[(s0 + t32) * ST + c0];
                #pragma unroll
                for (int q = 0; q < 6; q++) {
                    float f = colbuf[rr[q] * 32 + t32];
                    acc[q].x += f * pr.x; acc[q].y += f * pr.y;
                    acc[q].z += f * pr.z; acc[q].w += f * pr.w;
                }
            }
            bool in_s = (c0 >= s0 && c0 < s0 + 32);
            #pragma unroll
            for (int q = 0; q < 6; q++) {
                float4* p = (float4*)&M[rr[q] * ST + c0];
                if (in_s) {
                    *p = make_float4(-acc[q].x, -acc[q].y, -acc[q].z, -acc[q].w);
                } else {
                    float4 o = *p;
                    o.x -= acc[q].x; o.y -= acc[q].y; o.z -= acc[q].z; o.w -= acc[q].w;
                    *p = o;
                }
            }
        }
        __syncthreads();
    }

    for (int idx = tid; idx < NB * NB; idx += 512) {
        int r = idx >> 7, c = idx & 127;
        g_P[((size_t)b * NB + r) * NB + c] = M[r * ST + c];
    }
}

// ---------------- save column block ----------------
__global__ void gj_colcopy(int k, const int* __restrict__ lengths) {
    int b = blockIdx.x, rb = blockIdx.y;
    int len = lengths[b];
    int kb = k * NB;
    int r0 = rb * NB;
    if (kb >= len || r0 >= len) return;     // pad: column block rows are zero / unread
    int tid = threadIdx.x;                   // 256
    const float* lapb = g_lap + (size_t)b * NN * NN;
    float* colb = g_col + (size_t)b * NN * NB;
    for (int idx = tid; idx < 128 * 32; idx += 256) {
        int r = r0 + (idx >> 5);
        int c4 = (idx & 31) * 4;
        *(float4*)&colb[(size_t)r * NB + c4] =
            *(const float4*)&lapb[(size_t)r * NN + kb + c4];
    }
}

// ---------------- legacy-mma 128x128x128 GEMM (3xTF32), 256 threads ----------------
__device__ __forceinline__ uint32_t f2tf(float x) {
    uint32_t r; asm("cvt.rna.tf32.f32 %0, %1;" : "=r"(r) : "f"(x)); return r;
}
__device__ __forceinline__ void mma8(float4& d,
        uint32_t a0, uint32_t a1, uint32_t a2, uint32_t a3,
        uint32_t b0, uint32_t b1) {
    asm volatile("mma.sync.aligned.m16n8k8.row.col.f32.tf32.tf32.f32 "
        "{%0,%1,%2,%3}, {%4,%5,%6,%7}, {%8,%9}, {%0,%1,%2,%3};"
        : "+f"(d.x), "+f"(d.y), "+f"(d.z), "+f"(d.w)
        : "r"(a0), "r"(a1), "r"(a2), "r"(a3), "r"(b0), "r"(b1));
}

// smem buffers: buf[q]: A at q*4096, B at q*4096+2048 (float4 units). total 8192 f4 = 128KB.
__device__ __forceinline__ void load_raw(const float* __restrict__ Ag, int lda,
                                         const float* __restrict__ Bg, int ldb,
                                         int k0, int tid,
                                         float a_raw[4][4], float b_raw[8][2]) {
    #pragma unroll
    for (int it = 0; it < 4; it++) {
        int slot = it * 256 + tid;
        int l = slot & 31, mf = (slot >> 5) & 7, c = slot >> 8;
        int gg = l >> 2, tt = l & 3;
        int m = mf * 16 + gg, kk = k0 + c * 8 + tt;
        a_raw[it][0] = Ag[(size_t)m * lda + kk];
        a_raw[it][1] = Ag[(size_t)(m + 8) * lda + kk];
        a_raw[it][2] = Ag[(size_t)m * lda + kk + 4];
        a_raw[it][3] = Ag[(size_t)(m + 8) * lda + kk + 4];
    }
    #pragma unroll
    for (int it = 0; it < 8; it++) {
        int slot = it * 256 + tid;
        int l = slot & 31, nf = (slot >> 5) & 15, c = slot >> 9;
        int gg = l >> 2, tt = l & 3;
        int n = nf * 8 + gg, kk = k0 + c * 8 + tt;
        b_raw[it][0] = Bg[(size_t)kk * ldb + n];
        b_raw[it][1] = Bg[(size_t)(kk + 4) * ldb + n];
    }
}

__device__ __forceinline__ void cvt_store(float4* __restrict__ Apk, float4* __restrict__ Bpk,
                                          int tid,
                                          const float a_raw[4][4], const float b_raw[8][2]) {
    #pragma unroll
    for (int it = 0; it < 4; it++) {
        int slot = it * 256 + tid;
        int l = slot & 31, mf = (slot >> 5) & 7, c = slot >> 8;
        float a0 = a_raw[it][0], a1 = a_raw[it][1], a2 = a_raw[it][2], a3 = a_raw[it][3];
        uint32_t h0 = f2tf(a0), h1 = f2tf(a1), h2 = f2tf(a2), h3 = f2tf(a3);
        uint32_t l0 = f2tf(a0 - __uint_as_float(h0));
        uint32_t l1 = f2tf(a1 - __uint_as_float(h1));
        uint32_t l2 = f2tf(a2 - __uint_as_float(h2));
        uint32_t l3 = f2tf(a3 - __uint_as_float(h3));
        int base = (c * 8 + mf) * 64 + l;
        Apk[base]      = make_float4(__uint_as_float(h0), __uint_as_float(h1),
                                     __uint_as_float(h2), __uint_as_float(h3));
        Apk[base + 32] = make_float4(__uint_as_float(l0), __uint_as_float(l1),
                                     __uint_as_float(l2), __uint_as_float(l3));
    }
    #pragma unroll
    for (int it = 0; it < 8; it++) {
        int slot = it * 256 + tid;
        int l = slot & 31, nf = (slot >> 5) & 15, c = slot >> 9;
        float b0 = b_raw[it][0], b1 = b_raw[it][1];
        uint32_t h0 = f2tf(b0), h1 = f2tf(b1);
        uint32_t l0 = f2tf(b0 - __uint_as_float(h0));
        uint32_t l1 = f2tf(b1 - __uint_as_float(h1));
        Bpk[(c * 16 + nf) * 32 + l] =
            make_float4(__uint_as_float(h0), __uint_as_float(h1),
                        __uint_as_float(l0), __uint_as_float(l1));
    }
}

__device__ __forceinline__ void compute_chunk(const float4* __restrict__ Apk,
                                              const float4* __restrict__ Bpk,
                                              int lane, int wy, int wx, float4 acc[2][8]) {
    #pragma unroll
    for (int c = 0; c < 4; c++) {
        float4 af[2][2];
        #pragma unroll
        for (int i = 0; i < 2; i++) {
            int base = (c * 8 + wy * 2 + i) * 64 + lane;
            af[i][0] = Apk[base];
            af[i][1] = Apk[base + 32];
        }
        #pragma unroll
        for (int j = 0; j < 8; j++) {
            float4 bf = Bpk[(c * 16 + wx * 8 + j) * 32 + lane];
            uint32_t bh0 = __float_as_uint(bf.x), bh1 = __float_as_uint(bf.y);
            uint32_t bl0 = __float_as_uint(bf.z), bl1 = __float_as_uint(bf.w);
            #pragma unroll
            for (int i = 0; i < 2; i++) {
                uint32_t ah0 = __float_as_uint(af[i][0].x), ah1 = __float_as_uint(af[i][0].y);
                uint32_t ah2 = __float_as_uint(af[i][0].z), ah3 = __float_as_uint(af[i][0].w);
                uint32_t al0 = __float_as_uint(af[i][1].x), al1 = __float_as_uint(af[i][1].y);
                uint32_t al2 = __float_as_uint(af[i][1].z), al3 = __float_as_uint(af[i][1].w);
                mma8(acc[i][j], ah0, ah1, ah2, ah3, bh0, bh1);
                mma8(acc[i][j], ah0, ah1, ah2, ah3, bl0, bl1);
                mma8(acc[i][j], al0, al1, al2, al3, bh0, bh1);
            }
        }
    }
}

// C(128x128) = A(128x128, K-major, lda) * B stored [k][j] (ldb). 256 threads, double-buffered.
__device__ void gemm256(const float* __restrict__ Ag, int lda,
                        const float* __restrict__ Bg, int ldb, float4 acc[2][8]) {
    extern __shared__ float4 sm4[];
    int tid = threadIdx.x;
    int lane = tid & 31, w = tid >> 5;
    int wy = w >> 1, wx = w & 1;

    float a_raw[4][4]; float b_raw[8][2];
    load_raw(Ag, lda, Bg, ldb, 0, tid, a_raw, b_raw);
    cvt_store(sm4, sm4 + 2048, tid, a_raw, b_raw);
    __syncthreads();

    #pragma unroll
    for (int p = 0; p < 4; p++) {
        const float4* Apk = sm4 + (p & 1) * 4096;
        const float4* Bpk = Apk + 2048;
        if (p < 3) load_raw(Ag, lda, Bg, ldb, (p + 1) * 32, tid, a_raw, b_raw);
        compute_chunk(Apk, Bpk, lane, wy, wx, acc);
        if (p < 3) {
            float4* nA = sm4 + ((p + 1) & 1) * 4096;
            cvt_store(nA, nA + 2048, tid, a_raw, b_raw);
        }
        __syncthreads();
    }
}

// ---------------- row-panel update: A_kj <- P * A_kj ; A_kk <- P ----------------
__global__ void __launch_bounds__(256) gj_rowupd(int k, const int* __restrict__ lengths) {
    int jt = blockIdx.x, b = blockIdx.y;
    int len = lengths[b];
    int kb = k * NB, j0 = jt * NB;
    if (kb >= len) return;                      // pad step: nothing changes
    float* lapb = g_lap + (size_t)b * NN * NN;
    int tid = threadIdx.x;

    if (jt == k) {
        for (int idx = tid; idx < NB * NB / 4; idx += 256) {
            int r = idx >> 5, c4 = (idx & 31) * 4;
            *(float4*)&lapb[(size_t)(kb + r) * NN + kb + c4] =
                *(const float4*)&g_P[((size_t)b * NB + r) * NB + c4];
        }
        return;
    }
    if (j0 >= len) return;                      // pad panel is zero: P*0 = 0

    float4 acc[2][8];
    #pragma unroll
    for (int i = 0; i < 2; i++)
        #pragma unroll
        for (int j = 0; j < 8; j++) acc[i][j] = make_float4(0.f, 0.f, 0.f, 0.f);

    gemm256(g_P + (size_t)b * NB * NB, NB, lapb + (size_t)kb * NN + j0, NN, acc);

    int lane = tid & 31, w = tid >> 5, wy = w >> 1, wx = w & 1;
    int gg = lane >> 2, tt = lane & 3;
    #pragma unroll
    for (int i = 0; i < 2; i++) {
        int r0 = kb + wy * 32 + i * 16 + gg;
        #pragma unroll
        for (int j = 0; j < 8; j++) {
            int cc = j0 + wx * 64 + j * 8 + 2 * tt;
            *(float2*)&lapb[(size_t)r0 * NN + cc]       = make_float2(acc[i][j].x, acc[i][j].y);
            *(float2*)&lapb[(size_t)(r0 + 8) * NN + cc] = make_float2(acc[i][j].z, acc[i][j].w);
        }
    }
}

// ---------------- interior update ----------------
__global__ void __launch_bounds__(256) gj_interior(int k, const int* __restrict__ lengths) {
    int jt = blockIdx.x, it = blockIdx.y, b = blockIdx.z;
    if (it == k) return;
    int len = lengths[b];
    int i0 = it * NB, j0 = jt * NB, kb = k * NB;
    if (kb >= len) return;                      // pad step
    if (i0 >= len) return;                      // col rows zero
    if (j0 >= len && jt != k) return;           // pad panel zero
    float* lapb = g_lap + (size_t)b * NN * NN;
    const float* colb = g_col + (size_t)b * NN * NB;
    int tid = threadIdx.x;

    float4 acc[2][8];
    #pragma unroll
    for (int i = 0; i < 2; i++)
        #pragma unroll
        for (int j = 0; j < 8; j++) acc[i][j] = make_float4(0.f, 0.f, 0.f, 0.f);

    const float* Bg; int ldb;
    if (jt == k) { Bg = g_P + (size_t)b * NB * NB; ldb = NB; }
    else         { Bg = lapb + (size_t)kb * NN + j0; ldb = NN; }

    gemm256(colb + (size_t)i0 * NB, NB, Bg, ldb, acc);

    int lane = tid & 31, w = tid >> 5, wy = w >> 1, wx = w & 1;
    int gg = lane >> 2, tt = lane & 3;

    if (jt == k) {
        #pragma unroll
        for (int i = 0; i < 2; i++) {
            int r0 = i0 + wy * 32 + i * 16 + gg;
            #pragma unroll
            for (int j = 0; j < 8; j++) {
                int cc = kb + wx * 64 + j * 8 + 2 * tt;
                *(float2*)&lapb[(size_t)r0 * NN + cc]       = make_float2(-acc[i][j].x, -acc[i][j].y);
                *(float2*)&lapb[(size_t)(r0 + 8) * NN + cc] = make_float2(-acc[i][j].z, -acc[i][j].w);
            }
        }
    } else {
        #pragma unroll
        for (int i = 0; i < 2; i++) {
            int r0 = i0 + wy * 32 + i * 16 + gg;
            #pragma unroll
            for (int j = 0; j < 8; j++) {
                int cc = j0 + wx * 64 + j * 8 + 2 * tt;
                float2* p0 = (float2*)&lapb[(size_t)r0 * NN + cc];
                float2* p1 = (float2*)&lapb[(size_t)(r0 + 8) * NN + cc];
                float2 o0 = *p0, o1 = *p1;
                o0.x -= acc[i][j].x; o0.y -= acc[i][j].y;
                o1.x -= acc[i][j].z; o1.y -= acc[i][j].w;
                *p0 = o0; *p1 = o1;
            }
        }
    }
}

// ---------------- epilogue ----------------
__global__ void extract_diag() {
    int b = blockIdx.x;
    int t = threadIdx.x;  // 1024
    const float* invb = g_lap + (size_t)b * NN * NN;
    g_invdiag[b * NN + t] = invb[(size_t)t * NN + t];
    g_invcol0[b * NN + t] = invb[(size_t)t * NN];
}

__global__ void finalize(const int* __restrict__ lengths, float* __restrict__ out) {
    __shared__ float sm[32][33];
    int b = blockIdx.z;
    int i0 = blockIdx.y * 32, j0 = blockIdx.x * 32;
    int tx = threadIdx.x, ty = threadIdx.y;
    const float* invb = g_lap + (size_t)b * NN * NN;

    sm[ty][tx] = invb[(size_t)(j0 + ty) * NN + i0 + tx];
    __syncthreads();

    int i = i0 + ty, j = j0 + tx;
    int len = lengths[b];
    float res = 0.f;
    if (i < len && j < len) {
        float e = g_expS[(size_t)b * NN * NN + (size_t)i * NN + j];
        float t1 = (j == 0) ? 0.f : e * g_invdiag[b * NN + j];
        float t2 = (i == 0) ? 0.f : e * sm[tx][ty];      // inv[j][i]
        float root = (i == j) ? e * g_invcol0[b * NN + i] : 0.f;
        res = t1 - t2 + root;
    }
    out[(size_t)b * NN * NN + (size_t)i * NN + j] = res;
}

// ---------------- launch ----------------
extern "C" void kernel_launch(void* const* d_in, const int* in_sizes, int n_in,
                              void* d_out, int out_size) {
    const float* scores = (const float*)d_in[0];
    const int* lengths = (const int*)d_in[1];
    float* out = (float*)d_out;

    const int DIAG_SMEM = 128 * 132 * 4;   // 67584 (dynamic; statics ~38KB on top)
    const int GEMM_SMEM = 8192 * 16;       // 131072

    cudaFuncSetAttribute(gj_diaginv, cudaFuncAttributeMaxDynamicSharedMemorySize, DIAG_SMEM);
    cudaFuncSetAttribute(gj_rowupd, cudaFuncAttributeMaxDynamicSharedMemorySize, GEMM_SMEM);
    cudaFuncSetAttribute(gj_interior, cudaFuncAttributeMaxDynamicSharedMemorySize, GEMM_SMEM);

    build_exp<<<dim3(NN * NN / 256, BB), 256>>>(scores, lengths);
    colsum_k<<<BB, NN>>>(lengths);
    build_fill<<<dim3(NN * NN / 256, BB), 256>>>(lengths);

    for (int k = 0; k < NT; k++) {
        gj_diaginv<<<BB, 512, DIAG_SMEM>>>(k, lengths);
        gj_colcopy<<<dim3(BB, NT), 256>>>(k, lengths);
        gj_rowupd<<<dim3(NT, BB), 256, GEMM_SMEM>>>(k, lengths);
        gj_interior<<<dim3(NT, NT, BB), 256, GEMM_SMEM>>>(k, lengths);
    }

    extract_diag<<<BB, NN>>>();
    finalize<<<dim3(NN / 32, NN / 32, BB), dim3(32, 32)>>>(lengths, out);
}